// round 5
// baseline (speedup 1.0000x reference)
#include <cuda_runtime.h>

// ---------------------------------------------------------------------------
// GAT 3-layer GNN, N=50000 nodes, E=800000 edges (+50000 self loops),
// dims 256->128->128->128, heads=1, leaky_relu(0.2), global mean pool to 16.
//
// Inputs (metadata order):
//  0: x          float32 [50000,256]
//  1: edge_index int32   [2,800000]   (row 0 = src, row 1 = dst)
//  2: batch      int32   [50000]
//  3..6:  W0[256,128], as0[128], ad0[128], b0[128]
//  7..10: W1[128,128], as1, ad1, b1
//  11..14: W2[128,128], as2, ad2, b2
// Output: float32 [16,128]
// ---------------------------------------------------------------------------

#define N_NODES 50000
#define N_GRAPHS 16
#define E_EDGES 800000
#define E_TOT   (E_EDGES + N_NODES)
#define IN_DIM  256
#define HID     128
#define NEG_SLOPE 0.2f

// -------------------- device scratch (no allocations allowed) --------------
__device__ float g_h[N_NODES * HID];      // h = feat @ W  (pre-aggregation)
__device__ float g_feat[N_NODES * HID];   // aggregated node features
__device__ float g_als[N_NODES];
__device__ float g_ald[N_NODES];
__device__ int   g_rowptr[N_NODES + 1];
__device__ int   g_deg[N_NODES];
__device__ int   g_cursor[N_NODES];
__device__ int   g_csrc[E_TOT];
__device__ float g_pool[N_GRAPHS * HID];
__device__ float g_pcnt[N_GRAPHS];

// -------------------- CSR construction -------------------------------------
__global__ void k_zero() {
    int i = blockIdx.x * blockDim.x + threadIdx.x;
    if (i < N_NODES) g_deg[i] = 0;
    if (i < N_GRAPHS * HID) g_pool[i] = 0.f;
    if (i < N_GRAPHS) g_pcnt[i] = 0.f;
}

__global__ void k_count(const int* __restrict__ ei) {
    int i = blockIdx.x * blockDim.x + threadIdx.x;
    if (i >= E_TOT) return;
    int dst = (i < E_EDGES) ? ei[E_EDGES + i] : (i - E_EDGES);
    atomicAdd(&g_deg[dst], 1);
}

// single-block exclusive scan of g_deg -> g_rowptr (and primes g_cursor)
__global__ void k_scan() {
    __shared__ int s[1024];
    const int t = threadIdx.x;
    const int CH = (N_NODES + 1023) / 1024;   // 49
    const int base = t * CH;
    int sum = 0;
    for (int i = 0; i < CH; i++) {
        int v = base + i;
        if (v < N_NODES) sum += g_deg[v];
    }
    s[t] = sum;
    __syncthreads();
    for (int off = 1; off < 1024; off <<= 1) {
        int v = (t >= off) ? s[t - off] : 0;
        __syncthreads();
        s[t] += v;
        __syncthreads();
    }
    int run = (t > 0) ? s[t - 1] : 0;
    for (int i = 0; i < CH; i++) {
        int v = base + i;
        if (v < N_NODES) {
            g_rowptr[v] = run;
            g_cursor[v] = run;
            run += g_deg[v];
        }
    }
    if (t == 1023) g_rowptr[N_NODES] = s[1023];
}

__global__ void k_scatter(const int* __restrict__ ei) {
    int i = blockIdx.x * blockDim.x + threadIdx.x;
    if (i >= E_TOT) return;
    int src, dst;
    if (i < E_EDGES) { src = ei[i]; dst = ei[E_EDGES + i]; }
    else             { src = i - E_EDGES; dst = src; }
    int pos = atomicAdd(&g_cursor[dst], 1);
    g_csrc[pos] = src;
}

// -------------------- SGEMM: C[N,128] = A[N,K] @ W[K,128] ------------------
// BM=128, BN=128, BK=16, 256 threads, 8x8 microtile per thread.
// a_sel: 0 -> A = external pointer, 1 -> A = g_feat. Output always g_h.
__global__ __launch_bounds__(256) void k_gemm(const float* __restrict__ Aext,
                                              const float* __restrict__ W,
                                              int a_sel, int K) {
    const float* __restrict__ A = a_sel ? g_feat : Aext;
    float* __restrict__ C = g_h;
    __shared__ float As[16][128];   // transposed A tile: [k][row]
    __shared__ float Bs[16][128];   // [k][col]
    const int block_row = blockIdx.x * 128;
    const int tid = threadIdx.x;
    const int tx = tid & 15;        // col group
    const int ty = tid >> 4;        // row group
    float acc[8][8];
    #pragma unroll
    for (int i = 0; i < 8; i++)
        #pragma unroll
        for (int j = 0; j < 8; j++) acc[i][j] = 0.f;

    for (int k0 = 0; k0 < K; k0 += 16) {
        #pragma unroll
        for (int l = 0; l < 2; l++) {
            int v = tid + l * 256;
            // A tile: 128 rows x 16 k, float4 along K
            int row  = v >> 2;
            int kc4  = (v & 3) * 4;
            int grow = block_row + row;
            float4 a = make_float4(0.f, 0.f, 0.f, 0.f);
            if (grow < N_NODES)
                a = *(const float4*)&A[(size_t)grow * K + k0 + kc4];
            As[kc4 + 0][row] = a.x;
            As[kc4 + 1][row] = a.y;
            As[kc4 + 2][row] = a.z;
            As[kc4 + 3][row] = a.w;
            // B tile: 16 k x 128 cols
            int brow = v >> 5;
            int bcol = (v & 31) * 4;
            *(float4*)&Bs[brow][bcol] =
                *(const float4*)&W[(size_t)(k0 + brow) * HID + bcol];
        }
        __syncthreads();
        #pragma unroll
        for (int kk = 0; kk < 16; kk++) {
            float a[8], b[8];
            *(float4*)&a[0] = *(float4*)&As[kk][ty * 8];
            *(float4*)&a[4] = *(float4*)&As[kk][ty * 8 + 4];
            *(float4*)&b[0] = *(float4*)&Bs[kk][tx * 8];
            *(float4*)&b[4] = *(float4*)&Bs[kk][tx * 8 + 4];
            #pragma unroll
            for (int i = 0; i < 8; i++)
                #pragma unroll
                for (int j = 0; j < 8; j++)
                    acc[i][j] += a[i] * b[j];
        }
        __syncthreads();
    }
    #pragma unroll
    for (int i = 0; i < 8; i++) {
        int grow = block_row + ty * 8 + i;
        if (grow < N_NODES) {
            #pragma unroll
            for (int j = 0; j < 8; j += 4) {
                float4 o = make_float4(acc[i][j], acc[i][j + 1],
                                       acc[i][j + 2], acc[i][j + 3]);
                *(float4*)&C[(size_t)grow * HID + tx * 8 + j] = o;
            }
        }
    }
}

// -------------------- per-node attention logits ----------------------------
__global__ __launch_bounds__(256) void k_al(const float* __restrict__ a_s,
                                            const float* __restrict__ a_d) {
    int warp = (blockIdx.x * blockDim.x + threadIdx.x) >> 5;
    int lane = threadIdx.x & 31;
    if (warp >= N_NODES) return;
    float4 h = *(const float4*)&g_h[(size_t)warp * HID + lane * 4];
    float4 s = *(const float4*)&a_s[lane * 4];
    float4 d = *(const float4*)&a_d[lane * 4];
    float vs = h.x * s.x + h.y * s.y + h.z * s.z + h.w * s.w;
    float vd = h.x * d.x + h.y * d.y + h.z * d.z + h.w * d.w;
    #pragma unroll
    for (int o = 16; o; o >>= 1) {
        vs += __shfl_xor_sync(0xFFFFFFFFu, vs, o);
        vd += __shfl_xor_sync(0xFFFFFFFFu, vd, o);
    }
    if (lane == 0) { g_als[warp] = vs; g_ald[warp] = vd; }
}

// -------------------- softmax aggregation (one warp per dst node) ----------
__global__ __launch_bounds__(256) void k_agg(const float* __restrict__ bias,
                                             int relu_out) {
    float* __restrict__ outf = g_feat;
    __shared__ float coef[8][128];
    __shared__ int   srcs[8][128];
    const int wid  = threadIdx.x >> 5;
    const int lane = threadIdx.x & 31;
    const int v = blockIdx.x * 8 + wid;
    if (v >= N_NODES) return;
    const int beg = g_rowptr[v];
    const int end = g_rowptr[v + 1];
    const float adv = g_ald[v];

    // pass 1: segment max (lane-parallel over edges)
    float m = -1e30f;
    for (int e = beg + lane; e < end; e += 32) {
        float x = g_als[g_csrc[e]] + adv;
        x = (x > 0.f) ? x : NEG_SLOPE * x;
        m = fmaxf(m, x);
    }
    #pragma unroll
    for (int o = 16; o; o >>= 1) m = fmaxf(m, __shfl_xor_sync(0xFFFFFFFFu, m, o));

    // pass 2: chunked — lane-parallel exp into shared, then serial gather of h.
    float4 acc = make_float4(0.f, 0.f, 0.f, 0.f);
    float zpart = 0.f;
    for (int cb = beg; cb < end; cb += 128) {
        int cnt = min(128, end - cb);
        for (int i = lane; i < cnt; i += 32) {
            int s = g_csrc[cb + i];
            float x = g_als[s] + adv;
            x = (x > 0.f) ? x : NEG_SLOPE * x;
            float p = __expf(x - m);
            coef[wid][i] = p;
            srcs[wid][i] = s;
            zpart += p;
        }
        __syncwarp();
        for (int i = 0; i < cnt; i++) {
            int s   = srcs[wid][i];
            float p = coef[wid][i];
            const float4 h = *(const float4*)&g_h[(size_t)s * HID + lane * 4];
            acc.x += p * h.x; acc.y += p * h.y;
            acc.z += p * h.z; acc.w += p * h.w;
        }
        __syncwarp();
    }
    #pragma unroll
    for (int o = 16; o; o >>= 1) zpart += __shfl_xor_sync(0xFFFFFFFFu, zpart, o);
    const float inv = 1.f / zpart;   // self-loop guarantees zpart > 0

    float4 bb = *(const float4*)&bias[lane * 4];
    acc.x = acc.x * inv + bb.x;
    acc.y = acc.y * inv + bb.y;
    acc.z = acc.z * inv + bb.z;
    acc.w = acc.w * inv + bb.w;
    if (relu_out) {
        acc.x = fmaxf(acc.x, 0.f); acc.y = fmaxf(acc.y, 0.f);
        acc.z = fmaxf(acc.z, 0.f); acc.w = fmaxf(acc.w, 0.f);
    }
    *(float4*)&outf[(size_t)v * HID + lane * 4] = acc;
}

// -------------------- global mean pool -------------------------------------
__global__ __launch_bounds__(256) void k_pool(const int* __restrict__ batch) {
    __shared__ float s[N_GRAPHS * HID];
    __shared__ float sc[N_GRAPHS];
    const int tid = threadIdx.x;
    for (int i = tid; i < N_GRAPHS * HID; i += 256) s[i] = 0.f;
    if (tid < N_GRAPHS) sc[tid] = 0.f;
    __syncthreads();
    const int wid = tid >> 5, lane = tid & 31;
    for (int v = blockIdx.x * 8 + wid; v < N_NODES; v += gridDim.x * 8) {
        int g = batch[v];
        float4 f = *(const float4*)&g_feat[(size_t)v * HID + lane * 4];
        float* d = &s[g * HID + lane * 4];
        atomicAdd(d + 0, f.x); atomicAdd(d + 1, f.y);
        atomicAdd(d + 2, f.z); atomicAdd(d + 3, f.w);
        if (lane == 0) atomicAdd(&sc[g], 1.f);
    }
    __syncthreads();
    for (int i = tid; i < N_GRAPHS * HID; i += 256) atomicAdd(&g_pool[i], s[i]);
    if (tid < N_GRAPHS) atomicAdd(&g_pcnt[tid], sc[tid]);
}

__global__ void k_final(float* __restrict__ out) {
    int i = blockIdx.x * blockDim.x + threadIdx.x;
    if (i < N_GRAPHS * HID)
        out[i] = g_pool[i] / fmaxf(g_pcnt[i / HID], 1.f);
}

// -------------------- launch -----------------------------------------------
extern "C" void kernel_launch(void* const* d_in, const int* in_sizes, int n_in,
                              void* d_out, int out_size) {
    const float* x     = (const float*)d_in[0];
    const int*   ei    = (const int*)d_in[1];
    const int*   batch = (const int*)d_in[2];
    const float* W[3]  = { (const float*)d_in[3], (const float*)d_in[7],  (const float*)d_in[11] };
    const float* AS[3] = { (const float*)d_in[4], (const float*)d_in[8],  (const float*)d_in[12] };
    const float* AD[3] = { (const float*)d_in[5], (const float*)d_in[9],  (const float*)d_in[13] };
    const float* B[3]  = { (const float*)d_in[6], (const float*)d_in[10], (const float*)d_in[14] };
    float* out = (float*)d_out;

    const int ZB = (N_NODES + 255) / 256;          // 196
    const int EB = (E_TOT + 255) / 256;            // 3321
    const int GB = (N_NODES + 127) / 128;          // 391
    const int NB = (N_NODES + 7) / 8;              // 6250 (one warp/node)

    // CSR build (once; shared by all 3 layers)
    k_zero<<<ZB, 256>>>();
    k_count<<<EB, 256>>>(ei);
    k_scan<<<1, 1024>>>();
    k_scatter<<<EB, 256>>>(ei);

    // layer 0: x[*,256] -> feat (relu)
    k_gemm<<<GB, 256>>>(x, W[0], /*a_sel=*/0, IN_DIM);
    k_al<<<NB, 256>>>(AS[0], AD[0]);
    k_agg<<<NB, 256>>>(B[0], /*relu=*/1);

    // layer 1: feat -> feat (relu)
    k_gemm<<<GB, 256>>>(x, W[1], /*a_sel=*/1, HID);
    k_al<<<NB, 256>>>(AS[1], AD[1]);
    k_agg<<<NB, 256>>>(B[1], /*relu=*/1);

    // layer 2: feat -> node_emb (no relu)
    k_gemm<<<GB, 256>>>(x, W[2], /*a_sel=*/1, HID);
    k_al<<<NB, 256>>>(AS[2], AD[2]);
    k_agg<<<NB, 256>>>(B[2], /*relu=*/0);

    // global mean pool
    k_pool<<<148, 256>>>(batch);
    k_final<<<(N_GRAPHS * HID + 255) / 256, 256>>>(out);
}

// round 6
// speedup vs baseline: 1.0631x; 1.0631x over previous
#include <cuda_runtime.h>

// ---------------------------------------------------------------------------
// GAT 3-layer GNN, N=50000 nodes, E=800000 edges (+50000 self loops),
// dims 256->128->128->128, heads=1, leaky_relu(0.2), global mean pool to 16.
// R6: f32x2 packed-FMA GEMM + fused attention-logit epilogue.
// ---------------------------------------------------------------------------

#define N_NODES 50000
#define N_GRAPHS 16
#define E_EDGES 800000
#define E_TOT   (E_EDGES + N_NODES)
#define IN_DIM  256
#define HID     128
#define NEG_SLOPE 0.2f

typedef unsigned long long ull;

// -------------------- device scratch (no allocations allowed) --------------
__device__ float g_h[N_NODES * HID];      // h = feat @ W  (pre-aggregation)
__device__ float g_feat[N_NODES * HID];   // aggregated node features
__device__ float g_als[N_NODES];
__device__ float g_ald[N_NODES];
__device__ int   g_rowptr[N_NODES + 1];
__device__ int   g_deg[N_NODES];
__device__ int   g_cursor[N_NODES];
__device__ int   g_csrc[E_TOT];
__device__ float g_pool[N_GRAPHS * HID];
__device__ float g_pcnt[N_GRAPHS];

// -------------------- f32x2 helpers ----------------------------------------
__device__ __forceinline__ ull pack2(float lo, float hi) {
    ull r;
    asm("mov.b64 %0, {%1, %2};" : "=l"(r) : "f"(lo), "f"(hi));
    return r;
}
__device__ __forceinline__ void unpack2(ull v, float& lo, float& hi) {
    asm("mov.b64 {%0, %1}, %2;" : "=f"(lo), "=f"(hi) : "l"(v));
}
__device__ __forceinline__ ull ffma2(ull a, ull b, ull c) {
    ull d;
    asm("fma.rn.f32x2 %0, %1, %2, %3;" : "=l"(d) : "l"(a), "l"(b), "l"(c));
    return d;
}

// -------------------- CSR construction -------------------------------------
__global__ void k_zero() {
    int i = blockIdx.x * blockDim.x + threadIdx.x;
    if (i < N_NODES) g_deg[i] = 0;
    if (i < N_GRAPHS * HID) g_pool[i] = 0.f;
    if (i < N_GRAPHS) g_pcnt[i] = 0.f;
}

__global__ void k_count(const int* __restrict__ ei) {
    int i = blockIdx.x * blockDim.x + threadIdx.x;
    if (i >= E_TOT) return;
    int dst = (i < E_EDGES) ? ei[E_EDGES + i] : (i - E_EDGES);
    atomicAdd(&g_deg[dst], 1);
}

// single-block exclusive scan of g_deg -> g_rowptr (and primes g_cursor)
__global__ void k_scan() {
    __shared__ int s[1024];
    const int t = threadIdx.x;
    const int CH = (N_NODES + 1023) / 1024;   // 49
    const int base = t * CH;
    int sum = 0;
    for (int i = 0; i < CH; i++) {
        int v = base + i;
        if (v < N_NODES) sum += g_deg[v];
    }
    s[t] = sum;
    __syncthreads();
    for (int off = 1; off < 1024; off <<= 1) {
        int v = (t >= off) ? s[t - off] : 0;
        __syncthreads();
        s[t] += v;
        __syncthreads();
    }
    int run = (t > 0) ? s[t - 1] : 0;
    for (int i = 0; i < CH; i++) {
        int v = base + i;
        if (v < N_NODES) {
            g_rowptr[v] = run;
            g_cursor[v] = run;
            run += g_deg[v];
        }
    }
    if (t == 1023) g_rowptr[N_NODES] = s[1023];
}

__global__ void k_scatter(const int* __restrict__ ei) {
    int i = blockIdx.x * blockDim.x + threadIdx.x;
    if (i >= E_TOT) return;
    int src, dst;
    if (i < E_EDGES) { src = ei[i]; dst = ei[E_EDGES + i]; }
    else             { src = i - E_EDGES; dst = src; }
    int pos = atomicAdd(&g_cursor[dst], 1);
    g_csrc[pos] = src;
}

// -------------------- SGEMM + fused attention logits -----------------------
// C[N,128] = A[N,K] @ W[K,128]; also g_als = C.as, g_ald = C.ad per row.
// BM=128, BN=128, BK=16, 256 threads, 8x8 microtile, f32x2 packed FMA.
__global__ __launch_bounds__(256) void k_gemm(const float* __restrict__ Aext,
                                              const float* __restrict__ W,
                                              const float* __restrict__ a_s,
                                              const float* __restrict__ a_d,
                                              int a_sel, int K) {
    const float* __restrict__ A = a_sel ? g_feat : Aext;
    float* __restrict__ C = g_h;
    __shared__ float As[16][128];          // [k][row]
    __shared__ float Bs[16][128];          // [k][col]
    __shared__ float s_red[2][128][17];    // padded row-partial reduction
    const int block_row = blockIdx.x * 128;
    const int tid = threadIdx.x;
    const int tx = tid & 15;        // col group (cols tx*8 .. tx*8+7)
    const int ty = tid >> 4;        // row group (rows ty*8 .. ty*8+7)

    ull acc2[8][4];                 // [row][col-pair], lanes = (2jp, 2jp+1)
    #pragma unroll
    for (int i = 0; i < 8; i++)
        #pragma unroll
        for (int jp = 0; jp < 4; jp++) acc2[i][jp] = 0ull;

    for (int k0 = 0; k0 < K; k0 += 16) {
        #pragma unroll
        for (int l = 0; l < 2; l++) {
            int v = tid + l * 256;
            // A tile: 128 rows x 16 k, float4 along K
            int row  = v >> 2;
            int kc4  = (v & 3) * 4;
            int grow = block_row + row;
            float4 a = make_float4(0.f, 0.f, 0.f, 0.f);
            if (grow < N_NODES)
                a = *(const float4*)&A[(size_t)grow * K + k0 + kc4];
            As[kc4 + 0][row] = a.x;
            As[kc4 + 1][row] = a.y;
            As[kc4 + 2][row] = a.z;
            As[kc4 + 3][row] = a.w;
            // B tile: 16 k x 128 cols
            int brow = v >> 5;
            int bcol = (v & 31) * 4;
            *(float4*)&Bs[brow][bcol] =
                *(const float4*)&W[(size_t)(k0 + brow) * HID + bcol];
        }
        __syncthreads();
        #pragma unroll
        for (int kk = 0; kk < 16; kk++) {
            float a[8];
            *(float4*)&a[0] = *(float4*)&As[kk][ty * 8];
            *(float4*)&a[4] = *(float4*)&As[kk][ty * 8 + 4];
            ull ad2[8];
            #pragma unroll
            for (int i = 0; i < 8; i++) ad2[i] = pack2(a[i], a[i]);
            // b pairs straight from shared: consecutive floats = f32x2
            ulonglong2 bu0 = *(ulonglong2*)&Bs[kk][tx * 8];
            ulonglong2 bu1 = *(ulonglong2*)&Bs[kk][tx * 8 + 4];
            ull bp[4] = { bu0.x, bu0.y, bu1.x, bu1.y };
            #pragma unroll
            for (int i = 0; i < 8; i++)
                #pragma unroll
                for (int jp = 0; jp < 4; jp++)
                    acc2[i][jp] = ffma2(ad2[i], bp[jp], acc2[i][jp]);
        }
        __syncthreads();
    }

    // epilogue: unpack, store C, fused per-row attention-logit partials
    float as_r[8], ad_r[8];
    *(float4*)&as_r[0] = *(const float4*)&a_s[tx * 8];
    *(float4*)&as_r[4] = *(const float4*)&a_s[tx * 8 + 4];
    *(float4*)&ad_r[0] = *(const float4*)&a_d[tx * 8];
    *(float4*)&ad_r[4] = *(const float4*)&a_d[tx * 8 + 4];

    #pragma unroll
    for (int i = 0; i < 8; i++) {
        float c[8];
        #pragma unroll
        for (int jp = 0; jp < 4; jp++) unpack2(acc2[i][jp], c[2 * jp], c[2 * jp + 1]);
        int row  = ty * 8 + i;
        int grow = block_row + row;
        if (grow < N_NODES) {
            *(float4*)&C[(size_t)grow * HID + tx * 8]     = *(float4*)&c[0];
            *(float4*)&C[(size_t)grow * HID + tx * 8 + 4] = *(float4*)&c[4];
        }
        float ps = 0.f, pd = 0.f;
        #pragma unroll
        for (int j = 0; j < 8; j++) { ps += c[j] * as_r[j]; pd += c[j] * ad_r[j]; }
        s_red[0][row][tx] = ps;
        s_red[1][row][tx] = pd;
    }
    __syncthreads();
    if (tid < 128) {
        float ss = 0.f, sd = 0.f;
        #pragma unroll
        for (int t = 0; t < 16; t++) { ss += s_red[0][tid][t]; sd += s_red[1][tid][t]; }
        int grow = block_row + tid;
        if (grow < N_NODES) { g_als[grow] = ss; g_ald[grow] = sd; }
    }
}

// -------------------- softmax aggregation (one warp per dst node) ----------
__global__ __launch_bounds__(256) void k_agg(const float* __restrict__ bias,
                                             int relu_out) {
    float* __restrict__ outf = g_feat;
    __shared__ float coef[8][128];
    __shared__ int   srcs[8][128];
    const int wid  = threadIdx.x >> 5;
    const int lane = threadIdx.x & 31;
    const int v = blockIdx.x * 8 + wid;
    if (v >= N_NODES) return;
    const int beg = g_rowptr[v];
    const int end = g_rowptr[v + 1];
    const float adv = g_ald[v];

    // pass 1: segment max (lane-parallel over edges)
    float m = -1e30f;
    for (int e = beg + lane; e < end; e += 32) {
        float x = g_als[g_csrc[e]] + adv;
        x = (x > 0.f) ? x : NEG_SLOPE * x;
        m = fmaxf(m, x);
    }
    #pragma unroll
    for (int o = 16; o; o >>= 1) m = fmaxf(m, __shfl_xor_sync(0xFFFFFFFFu, m, o));

    // pass 2: chunked — lane-parallel exp into shared, then serial gather of h.
    float4 acc = make_float4(0.f, 0.f, 0.f, 0.f);
    float zpart = 0.f;
    for (int cb = beg; cb < end; cb += 128) {
        int cnt = min(128, end - cb);
        for (int i = lane; i < cnt; i += 32) {
            int s = g_csrc[cb + i];
            float x = g_als[s] + adv;
            x = (x > 0.f) ? x : NEG_SLOPE * x;
            float p = __expf(x - m);
            coef[wid][i] = p;
            srcs[wid][i] = s;
            zpart += p;
        }
        __syncwarp();
        for (int i = 0; i < cnt; i++) {
            int s   = srcs[wid][i];
            float p = coef[wid][i];
            const float4 h = *(const float4*)&g_h[(size_t)s * HID + lane * 4];
            acc.x += p * h.x; acc.y += p * h.y;
            acc.z += p * h.z; acc.w += p * h.w;
        }
        __syncwarp();
    }
    #pragma unroll
    for (int o = 16; o; o >>= 1) zpart += __shfl_xor_sync(0xFFFFFFFFu, zpart, o);
    const float inv = 1.f / zpart;   // self-loop guarantees zpart > 0

    float4 bb = *(const float4*)&bias[lane * 4];
    acc.x = acc.x * inv + bb.x;
    acc.y = acc.y * inv + bb.y;
    acc.z = acc.z * inv + bb.z;
    acc.w = acc.w * inv + bb.w;
    if (relu_out) {
        acc.x = fmaxf(acc.x, 0.f); acc.y = fmaxf(acc.y, 0.f);
        acc.z = fmaxf(acc.z, 0.f); acc.w = fmaxf(acc.w, 0.f);
    }
    *(float4*)&outf[(size_t)v * HID + lane * 4] = acc;
}

// -------------------- global mean pool -------------------------------------
__global__ __launch_bounds__(256) void k_pool(const int* __restrict__ batch) {
    __shared__ float s[N_GRAPHS * HID];
    __shared__ float sc[N_GRAPHS];
    const int tid = threadIdx.x;
    for (int i = tid; i < N_GRAPHS * HID; i += 256) s[i] = 0.f;
    if (tid < N_GRAPHS) sc[tid] = 0.f;
    __syncthreads();
    const int wid = tid >> 5, lane = tid & 31;
    for (int v = blockIdx.x * 8 + wid; v < N_NODES; v += gridDim.x * 8) {
        int g = batch[v];
        float4 f = *(const float4*)&g_feat[(size_t)v * HID + lane * 4];
        float* d = &s[g * HID + lane * 4];
        atomicAdd(d + 0, f.x); atomicAdd(d + 1, f.y);
        atomicAdd(d + 2, f.z); atomicAdd(d + 3, f.w);
        if (lane == 0) atomicAdd(&sc[g], 1.f);
    }
    __syncthreads();
    for (int i = tid; i < N_GRAPHS * HID; i += 256) atomicAdd(&g_pool[i], s[i]);
    if (tid < N_GRAPHS) atomicAdd(&g_pcnt[tid], sc[tid]);
}

__global__ void k_final(float* __restrict__ out) {
    int i = blockIdx.x * blockDim.x + threadIdx.x;
    if (i < N_GRAPHS * HID)
        out[i] = g_pool[i] / fmaxf(g_pcnt[i / HID], 1.f);
}

// -------------------- launch -----------------------------------------------
extern "C" void kernel_launch(void* const* d_in, const int* in_sizes, int n_in,
                              void* d_out, int out_size) {
    const float* x     = (const float*)d_in[0];
    const int*   ei    = (const int*)d_in[1];
    const int*   batch = (const int*)d_in[2];
    const float* W[3]  = { (const float*)d_in[3], (const float*)d_in[7],  (const float*)d_in[11] };
    const float* AS[3] = { (const float*)d_in[4], (const float*)d_in[8],  (const float*)d_in[12] };
    const float* AD[3] = { (const float*)d_in[5], (const float*)d_in[9],  (const float*)d_in[13] };
    const float* B[3]  = { (const float*)d_in[6], (const float*)d_in[10], (const float*)d_in[14] };
    float* out = (float*)d_out;

    const int ZB = (N_NODES + 255) / 256;          // 196
    const int EB = (E_TOT + 255) / 256;            // 3321
    const int GB = (N_NODES + 127) / 128;          // 391
    const int NB = (N_NODES + 7) / 8;              // 6250 (one warp/node)

    // CSR build (once; shared by all 3 layers)
    k_zero<<<ZB, 256>>>();
    k_count<<<EB, 256>>>(ei);
    k_scan<<<1, 1024>>>();
    k_scatter<<<EB, 256>>>(ei);

    // layer 0: x[*,256] -> feat (relu)
    k_gemm<<<GB, 256>>>(x, W[0], AS[0], AD[0], /*a_sel=*/0, IN_DIM);
    k_agg<<<NB, 256>>>(B[0], /*relu=*/1);

    // layer 1: feat -> feat (relu)
    k_gemm<<<GB, 256>>>(x, W[1], AS[1], AD[1], /*a_sel=*/1, HID);
    k_agg<<<NB, 256>>>(B[1], /*relu=*/1);

    // layer 2: feat -> node_emb (no relu)
    k_gemm<<<GB, 256>>>(x, W[2], AS[2], AD[2], /*a_sel=*/1, HID);
    k_agg<<<NB, 256>>>(B[2], /*relu=*/0);

    // global mean pool
    k_pool<<<148, 256>>>(batch);
    k_final<<<(N_GRAPHS * HID + 255) / 256, 256>>>(out);
}

// round 7
// speedup vs baseline: 1.1575x; 1.0888x over previous
#include <cuda_runtime.h>
#include <cuda_fp16.h>

// ---------------------------------------------------------------------------
// GAT 3-layer GNN, N=50000 nodes, E=800000 edges (+50000 self loops),
// dims 256->128->128->128, heads=1, leaky_relu(0.2), global mean pool to 16.
// R7: g_h stored as fp16 (halves edge-gather L2 traffic); fused logits;
//     f32x2 packed-FMA GEMM.
// ---------------------------------------------------------------------------

#define N_NODES 50000
#define N_GRAPHS 16
#define E_EDGES 800000
#define E_TOT   (E_EDGES + N_NODES)
#define IN_DIM  256
#define HID     128
#define NEG_SLOPE 0.2f

typedef unsigned long long ull;

// -------------------- device scratch (no allocations allowed) --------------
__device__ __half2 g_hh[N_NODES * (HID / 2)];  // h in fp16 (only agg reads it)
__device__ float   g_feat[N_NODES * HID];      // aggregated node features (fp32)
__device__ float   g_als[N_NODES];
__device__ float   g_ald[N_NODES];
__device__ int     g_rowptr[N_NODES + 1];
__device__ int     g_deg[N_NODES];
__device__ int     g_cursor[N_NODES];
__device__ int     g_csrc[E_TOT];
__device__ float   g_pool[N_GRAPHS * HID];
__device__ float   g_pcnt[N_GRAPHS];

// -------------------- f32x2 helpers ----------------------------------------
__device__ __forceinline__ ull pack2(float lo, float hi) {
    ull r;
    asm("mov.b64 %0, {%1, %2};" : "=l"(r) : "f"(lo), "f"(hi));
    return r;
}
__device__ __forceinline__ void unpack2(ull v, float& lo, float& hi) {
    asm("mov.b64 {%0, %1}, %2;" : "=f"(lo), "=f"(hi) : "l"(v));
}
__device__ __forceinline__ ull ffma2(ull a, ull b, ull c) {
    ull d;
    asm("fma.rn.f32x2 %0, %1, %2, %3;" : "=l"(d) : "l"(a), "l"(b), "l"(c));
    return d;
}

// -------------------- CSR construction -------------------------------------
__global__ void k_zero() {
    int i = blockIdx.x * blockDim.x + threadIdx.x;
    if (i < N_NODES) g_deg[i] = 0;
    if (i < N_GRAPHS * HID) g_pool[i] = 0.f;
    if (i < N_GRAPHS) g_pcnt[i] = 0.f;
}

__global__ void k_count(const int* __restrict__ ei) {
    int i = blockIdx.x * blockDim.x + threadIdx.x;
    if (i >= E_TOT) return;
    int dst = (i < E_EDGES) ? ei[E_EDGES + i] : (i - E_EDGES);
    atomicAdd(&g_deg[dst], 1);
}

// single-block exclusive scan of g_deg -> g_rowptr (and primes g_cursor)
__global__ void k_scan() {
    __shared__ int s[1024];
    const int t = threadIdx.x;
    const int CH = (N_NODES + 1023) / 1024;   // 49
    const int base = t * CH;
    int sum = 0;
    for (int i = 0; i < CH; i++) {
        int v = base + i;
        if (v < N_NODES) sum += g_deg[v];
    }
    s[t] = sum;
    __syncthreads();
    for (int off = 1; off < 1024; off <<= 1) {
        int v = (t >= off) ? s[t - off] : 0;
        __syncthreads();
        s[t] += v;
        __syncthreads();
    }
    int run = (t > 0) ? s[t - 1] : 0;
    for (int i = 0; i < CH; i++) {
        int v = base + i;
        if (v < N_NODES) {
            g_rowptr[v] = run;
            g_cursor[v] = run;
            run += g_deg[v];
        }
    }
    if (t == 1023) g_rowptr[N_NODES] = s[1023];
}

__global__ void k_scatter(const int* __restrict__ ei) {
    int i = blockIdx.x * blockDim.x + threadIdx.x;
    if (i >= E_TOT) return;
    int src, dst;
    if (i < E_EDGES) { src = ei[i]; dst = ei[E_EDGES + i]; }
    else             { src = i - E_EDGES; dst = src; }
    int pos = atomicAdd(&g_cursor[dst], 1);
    g_csrc[pos] = src;
}

// -------------------- SGEMM + fused attention logits -----------------------
// h[N,128] = A[N,K] @ W[K,128] stored fp16 to g_hh; g_als/g_ald fp32 per row.
// BM=128, BN=128, BK=16, 256 threads, 8x8 microtile, f32x2 packed FMA.
__global__ __launch_bounds__(256) void k_gemm(const float* __restrict__ Aext,
                                              const float* __restrict__ W,
                                              const float* __restrict__ a_s,
                                              const float* __restrict__ a_d,
                                              int a_sel, int K) {
    const float* __restrict__ A = a_sel ? g_feat : Aext;
    __shared__ float As[16][128];          // [k][row]
    __shared__ float Bs[16][128];          // [k][col]
    __shared__ float s_red[2][128][17];    // padded row-partial reduction
    const int block_row = blockIdx.x * 128;
    const int tid = threadIdx.x;
    const int tx = tid & 15;        // col group (cols tx*8 .. tx*8+7)
    const int ty = tid >> 4;        // row group (rows ty*8 .. ty*8+7)

    ull acc2[8][4];                 // [row][col-pair]
    #pragma unroll
    for (int i = 0; i < 8; i++)
        #pragma unroll
        for (int jp = 0; jp < 4; jp++) acc2[i][jp] = 0ull;

    for (int k0 = 0; k0 < K; k0 += 16) {
        #pragma unroll
        for (int l = 0; l < 2; l++) {
            int v = tid + l * 256;
            int row  = v >> 2;
            int kc4  = (v & 3) * 4;
            int grow = block_row + row;
            float4 a = make_float4(0.f, 0.f, 0.f, 0.f);
            if (grow < N_NODES)
                a = *(const float4*)&A[(size_t)grow * K + k0 + kc4];
            As[kc4 + 0][row] = a.x;
            As[kc4 + 1][row] = a.y;
            As[kc4 + 2][row] = a.z;
            As[kc4 + 3][row] = a.w;
            int brow = v >> 5;
            int bcol = (v & 31) * 4;
            *(float4*)&Bs[brow][bcol] =
                *(const float4*)&W[(size_t)(k0 + brow) * HID + bcol];
        }
        __syncthreads();
        #pragma unroll
        for (int kk = 0; kk < 16; kk++) {
            float a[8];
            *(float4*)&a[0] = *(float4*)&As[kk][ty * 8];
            *(float4*)&a[4] = *(float4*)&As[kk][ty * 8 + 4];
            ulonglong2 bu0 = *(ulonglong2*)&Bs[kk][tx * 8];
            ulonglong2 bu1 = *(ulonglong2*)&Bs[kk][tx * 8 + 4];
            ull bp[4] = { bu0.x, bu0.y, bu1.x, bu1.y };
            #pragma unroll
            for (int i = 0; i < 8; i++) {
                ull ai = pack2(a[i], a[i]);
                #pragma unroll
                for (int jp = 0; jp < 4; jp++)
                    acc2[i][jp] = ffma2(ai, bp[jp], acc2[i][jp]);
            }
        }
        __syncthreads();
    }

    // epilogue: unpack, store h (fp16), fused per-row attention-logit partials
    float as_r[8], ad_r[8];
    *(float4*)&as_r[0] = *(const float4*)&a_s[tx * 8];
    *(float4*)&as_r[4] = *(const float4*)&a_s[tx * 8 + 4];
    *(float4*)&ad_r[0] = *(const float4*)&a_d[tx * 8];
    *(float4*)&ad_r[4] = *(const float4*)&a_d[tx * 8 + 4];

    #pragma unroll
    for (int i = 0; i < 8; i++) {
        float c[8];
        #pragma unroll
        for (int jp = 0; jp < 4; jp++) unpack2(acc2[i][jp], c[2 * jp], c[2 * jp + 1]);
        int row  = ty * 8 + i;
        int grow = block_row + row;
        if (grow < N_NODES) {
            __half2 hc[4];
            #pragma unroll
            for (int jp = 0; jp < 4; jp++)
                hc[jp] = __floats2half2_rn(c[2 * jp], c[2 * jp + 1]);
            // 8 halves = 16 B per thread, row has 64 half2
            *(uint4*)&g_hh[(size_t)grow * (HID / 2) + tx * 4] = *(uint4*)hc;
        }
        float ps = 0.f, pd = 0.f;
        #pragma unroll
        for (int j = 0; j < 8; j++) { ps += c[j] * as_r[j]; pd += c[j] * ad_r[j]; }
        s_red[0][row][tx] = ps;
        s_red[1][row][tx] = pd;
    }
    __syncthreads();
    if (tid < 128) {
        float ss = 0.f, sd = 0.f;
        #pragma unroll
        for (int t = 0; t < 16; t++) { ss += s_red[0][tid][t]; sd += s_red[1][tid][t]; }
        int grow = block_row + tid;
        if (grow < N_NODES) { g_als[grow] = ss; g_ald[grow] = sd; }
    }
}

// -------------------- softmax aggregation (one warp per dst node) ----------
// lane handles 4 feature channels = 2 half2 = one 8B load per edge.
__global__ __launch_bounds__(256) void k_agg(const float* __restrict__ bias,
                                             int relu_out) {
    float* __restrict__ outf = g_feat;
    __shared__ float coef[8][128];
    __shared__ int   srcs[8][128];
    const int wid  = threadIdx.x >> 5;
    const int lane = threadIdx.x & 31;
    const int v = blockIdx.x * 8 + wid;
    if (v >= N_NODES) return;
    const int beg = g_rowptr[v];
    const int end = g_rowptr[v + 1];
    const float adv = g_ald[v];

    // pass 1: segment max (lane-parallel over edges)
    float m = -1e30f;
    for (int e = beg + lane; e < end; e += 32) {
        float x = g_als[g_csrc[e]] + adv;
        x = (x > 0.f) ? x : NEG_SLOPE * x;
        m = fmaxf(m, x);
    }
    #pragma unroll
    for (int o = 16; o; o >>= 1) m = fmaxf(m, __shfl_xor_sync(0xFFFFFFFFu, m, o));

    // pass 2: chunked — lane-parallel exp into shared, then gather of fp16 h.
    float4 acc = make_float4(0.f, 0.f, 0.f, 0.f);
    float zpart = 0.f;
    for (int cb = beg; cb < end; cb += 128) {
        int cnt = min(128, end - cb);
        for (int i = lane; i < cnt; i += 32) {
            int s = g_csrc[cb + i];
            float x = g_als[s] + adv;
            x = (x > 0.f) ? x : NEG_SLOPE * x;
            float p = __expf(x - m);
            coef[wid][i] = p;
            srcs[wid][i] = s;
            zpart += p;
        }
        __syncwarp();
        #pragma unroll 4
        for (int i = 0; i < cnt; i++) {
            int s   = srcs[wid][i];
            float p = coef[wid][i];
            uint2 raw = *(const uint2*)&g_hh[(size_t)s * (HID / 2) + lane * 2];
            float2 h0 = __half22float2(*(__half2*)&raw.x);
            float2 h1 = __half22float2(*(__half2*)&raw.y);
            acc.x += p * h0.x; acc.y += p * h0.y;
            acc.z += p * h1.x; acc.w += p * h1.y;
        }
        __syncwarp();
    }
    #pragma unroll
    for (int o = 16; o; o >>= 1) zpart += __shfl_xor_sync(0xFFFFFFFFu, zpart, o);
    const float inv = 1.f / zpart;   // self-loop guarantees zpart > 0

    float4 bb = *(const float4*)&bias[lane * 4];
    acc.x = acc.x * inv + bb.x;
    acc.y = acc.y * inv + bb.y;
    acc.z = acc.z * inv + bb.z;
    acc.w = acc.w * inv + bb.w;
    if (relu_out) {
        acc.x = fmaxf(acc.x, 0.f); acc.y = fmaxf(acc.y, 0.f);
        acc.z = fmaxf(acc.z, 0.f); acc.w = fmaxf(acc.w, 0.f);
    }
    *(float4*)&outf[(size_t)v * HID + lane * 4] = acc;
}

// -------------------- global mean pool -------------------------------------
__global__ __launch_bounds__(256) void k_pool(const int* __restrict__ batch) {
    __shared__ float s[N_GRAPHS * HID];
    __shared__ float sc[N_GRAPHS];
    const int tid = threadIdx.x;
    for (int i = tid; i < N_GRAPHS * HID; i += 256) s[i] = 0.f;
    if (tid < N_GRAPHS) sc[tid] = 0.f;
    __syncthreads();
    const int wid = tid >> 5, lane = tid & 31;
    for (int v = blockIdx.x * 8 + wid; v < N_NODES; v += gridDim.x * 8) {
        int g = batch[v];
        float4 f = *(const float4*)&g_feat[(size_t)v * HID + lane * 4];
        float* d = &s[g * HID + lane * 4];
        atomicAdd(d + 0, f.x); atomicAdd(d + 1, f.y);
        atomicAdd(d + 2, f.z); atomicAdd(d + 3, f.w);
        if (lane == 0) atomicAdd(&sc[g], 1.f);
    }
    __syncthreads();
    for (int i = tid; i < N_GRAPHS * HID; i += 256) atomicAdd(&g_pool[i], s[i]);
    if (tid < N_GRAPHS) atomicAdd(&g_pcnt[tid], sc[tid]);
}

__global__ void k_final(float* __restrict__ out) {
    int i = blockIdx.x * blockDim.x + threadIdx.x;
    if (i < N_GRAPHS * HID)
        out[i] = g_pool[i] / fmaxf(g_pcnt[i / HID], 1.f);
}

// -------------------- launch -----------------------------------------------
extern "C" void kernel_launch(void* const* d_in, const int* in_sizes, int n_in,
                              void* d_out, int out_size) {
    const float* x     = (const float*)d_in[0];
    const int*   ei    = (const int*)d_in[1];
    const int*   batch = (const int*)d_in[2];
    const float* W[3]  = { (const float*)d_in[3], (const float*)d_in[7],  (const float*)d_in[11] };
    const float* AS[3] = { (const float*)d_in[4], (const float*)d_in[8],  (const float*)d_in[12] };
    const float* AD[3] = { (const float*)d_in[5], (const float*)d_in[9],  (const float*)d_in[13] };
    const float* B[3]  = { (const float*)d_in[6], (const float*)d_in[10], (const float*)d_in[14] };
    float* out = (float*)d_out;

    const int ZB = (N_NODES + 255) / 256;          // 196
    const int EB = (E_TOT + 255) / 256;            // 3321
    const int GB = (N_NODES + 127) / 128;          // 391
    const int NB = (N_NODES + 7) / 8;              // 6250 (one warp/node)

    // CSR build (once; shared by all 3 layers)
    k_zero<<<ZB, 256>>>();
    k_count<<<EB, 256>>>(ei);
    k_scan<<<1, 1024>>>();
    k_scatter<<<EB, 256>>>(ei);

    // layer 0: x[*,256] -> feat (relu)
    k_gemm<<<GB, 256>>>(x, W[0], AS[0], AD[0], /*a_sel=*/0, IN_DIM);
    k_agg<<<NB, 256>>>(B[0], /*relu=*/1);

    // layer 1: feat -> feat (relu)
    k_gemm<<<GB, 256>>>(x, W[1], AS[1], AD[1], /*a_sel=*/1, HID);
    k_agg<<<NB, 256>>>(B[1], /*relu=*/1);

    // layer 2: feat -> node_emb (no relu)
    k_gemm<<<GB, 256>>>(x, W[2], AS[2], AD[2], /*a_sel=*/1, HID);
    k_agg<<<NB, 256>>>(B[2], /*relu=*/0);

    // global mean pool
    k_pool<<<148, 256>>>(batch);
    k_final<<<(N_GRAPHS * HID + 255) / 256, 256>>>(out);
}

// round 10
// speedup vs baseline: 1.5754x; 1.3611x over previous
#include <cuda_runtime.h>
#include <cuda_fp16.h>

// ---------------------------------------------------------------------------
// GAT 3-layer GNN, N=50000 nodes, E=800000 edges (+50000 self loops),
// dims 256->128->128->128, heads=1, leaky_relu(0.2), global mean pool to 16.
// R8: tensor-core GEMM (mma.sync m16n8k16 fp16 in / fp32 accum) with fused
//     attention logits; fp16 feature storage end-to-end; fp16 edge gather.
// ---------------------------------------------------------------------------

#define N_NODES 50000
#define N_GRAPHS 16
#define E_EDGES 800000
#define E_TOT   (E_EDGES + N_NODES)
#define IN_DIM  256
#define HID     128
#define NEG_SLOPE 0.2f

// -------------------- device scratch (no allocations allowed) --------------
__device__ __half  g_xh[N_NODES * IN_DIM];                 // x in fp16
__device__ __half  g_wh[IN_DIM * HID + 2 * HID * HID];     // W0|W1|W2 fp16
__device__ __half2 g_hh[N_NODES * (HID / 2)];              // h (pre-agg) fp16
__device__ __half2 g_fh[N_NODES * (HID / 2)];              // feat fp16 (next A)
__device__ float   g_feat[N_NODES * HID];                  // feat fp32 (pool)
__device__ float   g_als[N_NODES];
__device__ float   g_ald[N_NODES];
__device__ int     g_rowptr[N_NODES + 1];
__device__ int     g_deg[N_NODES];
__device__ int     g_cursor[N_NODES];
__device__ int     g_csrc[E_TOT];
__device__ float   g_pool[N_GRAPHS * HID];
__device__ float   g_pcnt[N_GRAPHS];

// -------------------- fp32 -> fp16 conversion ------------------------------
__global__ void k_cvt(const float* __restrict__ src, __half* __restrict__ dst,
                      int n4) {
    int i = blockIdx.x * blockDim.x + threadIdx.x;
    if (i >= n4) return;
    float4 v = ((const float4*)src)[i];
    __half2 h0 = __floats2half2_rn(v.x, v.y);
    __half2 h1 = __floats2half2_rn(v.z, v.w);
    uint2 o;
    o.x = *(unsigned*)&h0;
    o.y = *(unsigned*)&h1;
    ((uint2*)dst)[i] = o;
}

// -------------------- CSR construction -------------------------------------
__global__ void k_zero() {
    int i = blockIdx.x * blockDim.x + threadIdx.x;
    if (i < N_NODES) g_deg[i] = 0;
    if (i < N_GRAPHS * HID) g_pool[i] = 0.f;
    if (i < N_GRAPHS) g_pcnt[i] = 0.f;
}

__global__ void k_count(const int* __restrict__ ei) {
    int i = blockIdx.x * blockDim.x + threadIdx.x;
    if (i >= E_TOT) return;
    int dst = (i < E_EDGES) ? ei[E_EDGES + i] : (i - E_EDGES);
    atomicAdd(&g_deg[dst], 1);
}

__global__ void k_scan() {
    __shared__ int s[1024];
    const int t = threadIdx.x;
    const int CH = (N_NODES + 1023) / 1024;   // 49
    const int base = t * CH;
    int sum = 0;
    for (int i = 0; i < CH; i++) {
        int v = base + i;
        if (v < N_NODES) sum += g_deg[v];
    }
    s[t] = sum;
    __syncthreads();
    for (int off = 1; off < 1024; off <<= 1) {
        int v = (t >= off) ? s[t - off] : 0;
        __syncthreads();
        s[t] += v;
        __syncthreads();
    }
    int run = (t > 0) ? s[t - 1] : 0;
    for (int i = 0; i < CH; i++) {
        int v = base + i;
        if (v < N_NODES) {
            g_rowptr[v] = run;
            g_cursor[v] = run;
            run += g_deg[v];
        }
    }
    if (t == 1023) g_rowptr[N_NODES] = s[1023];
}

__global__ void k_scatter(const int* __restrict__ ei) {
    int i = blockIdx.x * blockDim.x + threadIdx.x;
    if (i >= E_TOT) return;
    int src, dst;
    if (i < E_EDGES) { src = ei[i]; dst = ei[E_EDGES + i]; }
    else             { src = i - E_EDGES; dst = src; }
    int pos = atomicAdd(&g_cursor[dst], 1);
    g_csrc[pos] = src;
}

// -------------------- tensor-core GEMM + fused attention logits ------------
// h[N,128] = A[N,K](fp16) @ W[K,128](fp16), fp32 accum -> g_hh fp16 + logits.
// 128x128 block, 8 warps (warp tile 32x64), BK=32, mma m16n8k16.
__device__ __forceinline__ void mma16816(float* c, const unsigned* a,
                                         unsigned b0, unsigned b1) {
    asm volatile(
        "mma.sync.aligned.m16n8k16.row.col.f32.f16.f16.f32 "
        "{%0,%1,%2,%3}, {%4,%5,%6,%7}, {%8,%9}, {%0,%1,%2,%3};"
        : "+f"(c[0]), "+f"(c[1]), "+f"(c[2]), "+f"(c[3])
        : "r"(a[0]), "r"(a[1]), "r"(a[2]), "r"(a[3]), "r"(b0), "r"(b1));
}

__global__ __launch_bounds__(256) void k_gemm(const __half* __restrict__ Ah,
                                              const float* __restrict__ a_s,
                                              const float* __restrict__ a_d,
                                              int w_off, int K) {
    const __half* __restrict__ Wh = g_wh + w_off;
    __shared__ __align__(16) __half sA[128 * 40];   // stride 40 (pad 8)
    __shared__ __align__(16) __half sB[32 * 136];   // stride 136 (pad 8)
    __shared__ float s_red[2][2][128];
    const int tid    = threadIdx.x;
    const int lane   = tid & 31;
    const int wid    = tid >> 5;
    const int warp_m = wid & 3;     // 4 warps along M (32 rows each)
    const int warp_n = wid >> 2;    // 2 warps along N (64 cols each)
    const int block_row = blockIdx.x * 128;

    float c[2][8][4];
    #pragma unroll
    for (int mt = 0; mt < 2; mt++)
        #pragma unroll
        for (int nt = 0; nt < 8; nt++)
            #pragma unroll
            for (int q = 0; q < 4; q++) c[mt][nt][q] = 0.f;

    for (int k0 = 0; k0 < K; k0 += 32) {
        #pragma unroll
        for (int l = 0; l < 2; l++) {
            int ch = tid + l * 256;
            // A: 128 rows x 32 halves, 8 halves per chunk
            int row = ch >> 2, ko = (ch & 3) * 8;
            int grow = block_row + row;
            uint4 v = make_uint4(0u, 0u, 0u, 0u);
            if (grow < N_NODES)
                v = *(const uint4*)&Ah[(size_t)grow * K + k0 + ko];
            *(uint4*)&sA[row * 40 + ko] = v;
            // B: 32 k x 128 cols
            int kr = ch >> 4, no = (ch & 15) * 8;
            *(uint4*)&sB[kr * 136 + no] =
                *(const uint4*)&Wh[(size_t)(k0 + kr) * HID + no];
        }
        __syncthreads();
        #pragma unroll
        for (int ks = 0; ks < 2; ks++) {
            unsigned af[2][4];
            #pragma unroll
            for (int mt = 0; mt < 2; mt++) {
                unsigned sa = (unsigned)__cvta_generic_to_shared(
                    &sA[(warp_m * 32 + mt * 16 + (lane & 15)) * 40 +
                        ks * 16 + (lane >> 4) * 8]);
                asm volatile(
                    "ldmatrix.sync.aligned.m8n8.x4.shared.b16 {%0,%1,%2,%3}, [%4];"
                    : "=r"(af[mt][0]), "=r"(af[mt][1]),
                      "=r"(af[mt][2]), "=r"(af[mt][3]) : "r"(sa));
            }
            #pragma unroll
            for (int np = 0; np < 4; np++) {
                unsigned b0, b1, b2, b3;
                unsigned sb = (unsigned)__cvta_generic_to_shared(
                    &sB[(ks * 16 + ((lane >> 3) & 1) * 8 + (lane & 7)) * 136 +
                        warp_n * 64 + np * 16 + (lane >> 4) * 8]);
                asm volatile(
                    "ldmatrix.sync.aligned.m8n8.x4.trans.shared.b16 "
                    "{%0,%1,%2,%3}, [%4];"
                    : "=r"(b0), "=r"(b1), "=r"(b2), "=r"(b3) : "r"(sb));
                #pragma unroll
                for (int mt = 0; mt < 2; mt++) {
                    mma16816(c[mt][2 * np],     af[mt], b0, b1);
                    mma16816(c[mt][2 * np + 1], af[mt], b2, b3);
                }
            }
        }
        __syncthreads();
    }

    // ---- epilogue: store h fp16 + fused attention-logit reduction ----
    float2 as2[8], ad2[8];
    #pragma unroll
    for (int nt = 0; nt < 8; nt++) {
        int n0 = warp_n * 64 + nt * 8 + (lane & 3) * 2;
        as2[nt] = *(const float2*)&a_s[n0];
        ad2[nt] = *(const float2*)&a_d[n0];
    }
    float ps[2][2] = {{0.f, 0.f}, {0.f, 0.f}};
    float pd[2][2] = {{0.f, 0.f}, {0.f, 0.f}};
    #pragma unroll
    for (int mt = 0; mt < 2; mt++) {
        int r0 = block_row + warp_m * 32 + mt * 16 + (lane >> 2);
        #pragma unroll
        for (int nt = 0; nt < 8; nt++) {
            float* cc = c[mt][nt];
            int hcol = warp_n * 32 + nt * 4 + (lane & 3);
            if (r0 < N_NODES)
                g_hh[(size_t)r0 * 64 + hcol] = __floats2half2_rn(cc[0], cc[1]);
            if (r0 + 8 < N_NODES)
                g_hh[(size_t)(r0 + 8) * 64 + hcol] = __floats2half2_rn(cc[2], cc[3]);
            ps[mt][0] += cc[0] * as2[nt].x + cc[1] * as2[nt].y;
            ps[mt][1] += cc[2] * as2[nt].x + cc[3] * as2[nt].y;
            pd[mt][0] += cc[0] * ad2[nt].x + cc[1] * ad2[nt].y;
            pd[mt][1] += cc[2] * ad2[nt].x + cc[3] * ad2[nt].y;
        }
    }
    #pragma unroll
    for (int o = 1; o <= 2; o <<= 1) {
        #pragma unroll
        for (int mt = 0; mt < 2; mt++)
            #pragma unroll
            for (int rh = 0; rh < 2; rh++) {
                ps[mt][rh] += __shfl_xor_sync(0xFFFFFFFFu, ps[mt][rh], o);
                pd[mt][rh] += __shfl_xor_sync(0xFFFFFFFFu, pd[mt][rh], o);
            }
    }
    if ((lane & 3) == 0) {
        #pragma unroll
        for (int mt = 0; mt < 2; mt++)
            #pragma unroll
            for (int rh = 0; rh < 2; rh++) {
                int row = warp_m * 32 + mt * 16 + rh * 8 + (lane >> 2);
                s_red[0][warp_n][row] = ps[mt][rh];
                s_red[1][warp_n][row] = pd[mt][rh];
            }
    }
    __syncthreads();
    if (tid < 128) {
        int grow = block_row + tid;
        if (grow < N_NODES) {
            g_als[grow] = s_red[0][0][tid] + s_red[0][1][tid];
            g_ald[grow] = s_red[1][0][tid] + s_red[1][1][tid];
        }
    }
}

// -------------------- softmax aggregation (one warp per dst node) ----------
__global__ __launch_bounds__(256) void k_agg(const float* __restrict__ bias,
                                             int last) {
    __shared__ float coef[8][128];
    __shared__ int   srcs[8][128];
    const int wid  = threadIdx.x >> 5;
    const int lane = threadIdx.x & 31;
    const int v = blockIdx.x * 8 + wid;
    if (v >= N_NODES) return;
    const int beg = g_rowptr[v];
    const int end = g_rowptr[v + 1];
    const float adv = g_ald[v];

    // pass 1: segment max
    float m = -1e30f;
    for (int e = beg + lane; e < end; e += 32) {
        float x = g_als[g_csrc[e]] + adv;
        x = (x > 0.f) ? x : NEG_SLOPE * x;
        m = fmaxf(m, x);
    }
    #pragma unroll
    for (int o = 16; o; o >>= 1) m = fmaxf(m, __shfl_xor_sync(0xFFFFFFFFu, m, o));

    // pass 2: chunked — lane-parallel exp into shared, then gather of fp16 h.
    float4 acc = make_float4(0.f, 0.f, 0.f, 0.f);
    float zpart = 0.f;
    for (int cb = beg; cb < end; cb += 128) {
        int cnt = min(128, end - cb);
        for (int i = lane; i < cnt; i += 32) {
            int s = g_csrc[cb + i];
            float x = g_als[s] + adv;
            x = (x > 0.f) ? x : NEG_SLOPE * x;
            float p = __expf(x - m);
            coef[wid][i] = p;
            srcs[wid][i] = s;
            zpart += p;
        }
        __syncwarp();
        #pragma unroll 4
        for (int i = 0; i < cnt; i++) {
            int s   = srcs[wid][i];
            float p = coef[wid][i];
            uint2 raw = *(const uint2*)&g_hh[(size_t)s * (HID / 2) + lane * 2];
            float2 h0 = __half22float2(*(__half2*)&raw.x);
            float2 h1 = __half22float2(*(__half2*)&raw.y);
            acc.x += p * h0.x; acc.y += p * h0.y;
            acc.z += p * h1.x; acc.w += p * h1.y;
        }
        __syncwarp();
    }
    #pragma unroll
    for (int o = 16; o; o >>= 1) zpart += __shfl_xor_sync(0xFFFFFFFFu, zpart, o);
    const float inv = 1.f / zpart;   // self-loop guarantees zpart > 0

    float4 bb = *(const float4*)&bias[lane * 4];
    acc.x = acc.x * inv + bb.x;
    acc.y = acc.y * inv + bb.y;
    acc.z = acc.z * inv + bb.z;
    acc.w = acc.w * inv + bb.w;
    if (!last) {   // hidden layers: relu, fp16 copy feeds next GEMM
        acc.x = fmaxf(acc.x, 0.f); acc.y = fmaxf(acc.y, 0.f);
        acc.z = fmaxf(acc.z, 0.f); acc.w = fmaxf(acc.w, 0.f);
        __half2 f0 = __floats2half2_rn(acc.x, acc.y);
        __half2 f1 = __floats2half2_rn(acc.z, acc.w);
        uint2 u;
        u.x = *(unsigned*)&f0;
        u.y = *(unsigned*)&f1;
        *(uint2*)&g_fh[(size_t)v * (HID / 2) + lane * 2] = u;
    } else {       // last layer: fp32 for exact pooling
        *(float4*)&g_feat[(size_t)v * HID + lane * 4] = acc;
    }
}

// -------------------- global mean pool -------------------------------------
__global__ __launch_bounds__(256) void k_pool(const int* __restrict__ batch) {
    __shared__ float s[N_GRAPHS * HID];
    __shared__ float sc[N_GRAPHS];
    const int tid = threadIdx.x;
    for (int i = tid; i < N_GRAPHS * HID; i += 256) s[i] = 0.f;
    if (tid < N_GRAPHS) sc[tid] = 0.f;
    __syncthreads();
    const int wid = tid >> 5, lane = tid & 31;
    for (int v = blockIdx.x * 8 + wid; v < N_NODES; v += gridDim.x * 8) {
        int g = batch[v];
        float4 f = *(const float4*)&g_feat[(size_t)v * HID + lane * 4];
        float* d = &s[g * HID + lane * 4];
        atomicAdd(d + 0, f.x); atomicAdd(d + 1, f.y);
        atomicAdd(d + 2, f.z); atomicAdd(d + 3, f.w);
        if (lane == 0) atomicAdd(&sc[g], 1.f);
    }
    __syncthreads();
    for (int i = tid; i < N_GRAPHS * HID; i += 256) atomicAdd(&g_pool[i], s[i]);
    if (tid < N_GRAPHS) atomicAdd(&g_pcnt[tid], sc[tid]);
}

__global__ void k_final(float* __restrict__ out) {
    int i = blockIdx.x * blockDim.x + threadIdx.x;
    if (i < N_GRAPHS * HID)
        out[i] = g_pool[i] / fmaxf(g_pcnt[i / HID], 1.f);
}

// -------------------- launch -----------------------------------------------
extern "C" void kernel_launch(void* const* d_in, const int* in_sizes, int n_in,
                              void* d_out, int out_size) {
    const float* x     = (const float*)d_in[0];
    const int*   ei    = (const int*)d_in[1];
    const int*   batch = (const int*)d_in[2];
    const float* W[3]  = { (const float*)d_in[3], (const float*)d_in[7],  (const float*)d_in[11] };
    const float* AS[3] = { (const float*)d_in[4], (const float*)d_in[8],  (const float*)d_in[12] };
    const float* AD[3] = { (const float*)d_in[5], (const float*)d_in[9],  (const float*)d_in[13] };
    const float* B[3]  = { (const float*)d_in[6], (const float*)d_in[10], (const float*)d_in[14] };
    float* out = (float*)d_out;

    __half *d_xh, *d_wh;
    __half2* d_fh;
    cudaGetSymbolAddress((void**)&d_xh, g_xh);
    cudaGetSymbolAddress((void**)&d_wh, g_wh);
    cudaGetSymbolAddress((void**)&d_fh, g_fh);

    const int ZB = (N_NODES + 255) / 256;
    const int EB = (E_TOT + 255) / 256;
    const int GB = (N_NODES + 127) / 128;          // 391
    const int NB = (N_NODES + 7) / 8;              // 6250

    // fp16 conversions
    k_cvt<<<(N_NODES * IN_DIM / 4 + 255) / 256, 256>>>(x, d_xh, N_NODES * IN_DIM / 4);
    k_cvt<<<32, 256>>>(W[0], d_wh,                       IN_DIM * HID / 4);
    k_cvt<<<16, 256>>>(W[1], d_wh + IN_DIM * HID,        HID * HID / 4);
    k_cvt<<<16, 256>>>(W[2], d_wh + IN_DIM * HID + HID * HID, HID * HID / 4);

    // CSR build (once; shared by all 3 layers)
    k_zero<<<ZB, 256>>>();
    k_count<<<EB, 256>>>(ei);
    k_scan<<<1, 1024>>>();
    k_scatter<<<EB, 256>>>(ei);

    // layer 0
    k_gemm<<<GB, 256>>>(d_xh, AS[0], AD[0], 0, IN_DIM);
    k_agg<<<NB, 256>>>(B[0], /*last=*/0);
    // layer 1
    k_gemm<<<GB, 256>>>((const __half*)d_fh, AS[1], AD[1], IN_DIM * HID, HID);
    k_agg<<<NB, 256>>>(B[1], /*last=*/0);
    // layer 2
    k_gemm<<<GB, 256>>>((const __half*)d_fh, AS[2], AD[2],
                        IN_DIM * HID + HID * HID, HID);
    k_agg<<<NB, 256>>>(B[2], /*last=*/1);

    // global mean pool
    k_pool<<<148, 256>>>(batch);
    k_final<<<(N_GRAPHS * HID + 255) / 256, 256>>>(out);
}

// round 11
// speedup vs baseline: 1.7507x; 1.1113x over previous
#include <cuda_runtime.h>
#include <cuda_fp16.h>

// ---------------------------------------------------------------------------
// GAT 3-layer GNN, N=50000 nodes, E=800000 edges (+50000 self loops),
// dims 256->128->128->128, heads=1, leaky_relu(0.2), global mean pool to 16.
// R11: merged prep kernel; int4 CSR build; reg-prefetch pipelined tensor-core
//      GEMM; staged-logit agg fast path; fp16 pooling path (g_feat removed).
// ---------------------------------------------------------------------------

#define N_NODES 50000
#define N_GRAPHS 16
#define E_EDGES 800000
#define E_TOT   (E_EDGES + N_NODES)
#define IN_DIM  256
#define HID     128
#define NEG_SLOPE 0.2f

// -------------------- device scratch (no allocations allowed) --------------
__device__ __half  g_xh[N_NODES * IN_DIM];                 // x in fp16
__device__ __half  g_wh[IN_DIM * HID + 2 * HID * HID];     // W0|W1|W2 fp16
__device__ __half2 g_hh[N_NODES * (HID / 2)];              // h (pre-agg) fp16
__device__ __half2 g_fh[N_NODES * (HID / 2)];              // feat fp16
__device__ float   g_als[N_NODES];
__device__ float   g_ald[N_NODES];
__device__ int     g_rowptr[N_NODES + 1];
__device__ int     g_deg[N_NODES];
__device__ int     g_cursor[N_NODES];
__device__ int     g_csrc[E_TOT];
__device__ float   g_pool[N_GRAPHS * HID];
__device__ float   g_pcnt[N_GRAPHS];

// -------------------- merged prep: fp16 conversions + zeroing --------------
__device__ __forceinline__ void cvt4(const float* __restrict__ s,
                                     __half* __restrict__ d, int i) {
    float4 v = ((const float4*)s)[i];
    __half2 h0 = __floats2half2_rn(v.x, v.y);
    __half2 h1 = __floats2half2_rn(v.z, v.w);
    uint2 o;
    o.x = *(unsigned*)&h0;
    o.y = *(unsigned*)&h1;
    ((uint2*)d)[i] = o;
}

#define NX4 (N_NODES * IN_DIM / 4)     // 3,200,000
#define W04 (IN_DIM * HID / 4)         // 8,192
#define W14 (HID * HID / 4)            // 4,096
#define PREP_TOT (NX4 + W04 + 2 * W14 + N_NODES + N_GRAPHS * HID + N_GRAPHS)

__global__ void k_prep(const float* __restrict__ x,
                       const float* __restrict__ w0,
                       const float* __restrict__ w1,
                       const float* __restrict__ w2) {
    int i = blockIdx.x * blockDim.x + threadIdx.x;
    if (i < NX4) { cvt4(x, g_xh, i); return; }
    i -= NX4;
    if (i < W04) { cvt4(w0, g_wh, i); return; }
    i -= W04;
    if (i < W14) { cvt4(w1, g_wh + IN_DIM * HID, i); return; }
    i -= W14;
    if (i < W14) { cvt4(w2, g_wh + IN_DIM * HID + HID * HID, i); return; }
    i -= W14;
    if (i < N_NODES) { g_deg[i] = 0; return; }
    i -= N_NODES;
    if (i < N_GRAPHS * HID) { g_pool[i] = 0.f; return; }
    i -= N_GRAPHS * HID;
    if (i < N_GRAPHS) g_pcnt[i] = 0.f;
}

// -------------------- CSR construction (int4 edge loads) --------------------
#define EV4 (E_EDGES / 4)   // 200,000

__global__ void k_count(const int* __restrict__ ei) {
    int i = blockIdx.x * blockDim.x + threadIdx.x;
    if (i < EV4) {
        int4 d = ((const int4*)(ei + E_EDGES))[i];
        atomicAdd(&g_deg[d.x], 1);
        atomicAdd(&g_deg[d.y], 1);
        atomicAdd(&g_deg[d.z], 1);
        atomicAdd(&g_deg[d.w], 1);
    } else {
        int j = i - EV4;
        if (j < N_NODES) atomicAdd(&g_deg[j], 1);   // self loop
    }
}

__global__ void k_scan() {
    __shared__ int s[1024];
    const int t = threadIdx.x;
    const int CH = (N_NODES + 1023) / 1024;   // 49
    const int base = t * CH;
    int sum = 0;
    for (int i = 0; i < CH; i++) {
        int v = base + i;
        if (v < N_NODES) sum += g_deg[v];
    }
    s[t] = sum;
    __syncthreads();
    for (int off = 1; off < 1024; off <<= 1) {
        int v = (t >= off) ? s[t - off] : 0;
        __syncthreads();
        s[t] += v;
        __syncthreads();
    }
    int run = (t > 0) ? s[t - 1] : 0;
    for (int i = 0; i < CH; i++) {
        int v = base + i;
        if (v < N_NODES) {
            g_rowptr[v] = run;
            g_cursor[v] = run;
            run += g_deg[v];
        }
    }
    if (t == 1023) g_rowptr[N_NODES] = s[1023];
}

__global__ void k_scatter(const int* __restrict__ ei) {
    int i = blockIdx.x * blockDim.x + threadIdx.x;
    if (i < EV4) {
        int4 s4 = ((const int4*)ei)[i];
        int4 d4 = ((const int4*)(ei + E_EDGES))[i];
        g_csrc[atomicAdd(&g_cursor[d4.x], 1)] = s4.x;
        g_csrc[atomicAdd(&g_cursor[d4.y], 1)] = s4.y;
        g_csrc[atomicAdd(&g_cursor[d4.z], 1)] = s4.z;
        g_csrc[atomicAdd(&g_cursor[d4.w], 1)] = s4.w;
    } else {
        int j = i - EV4;
        if (j < N_NODES) g_csrc[atomicAdd(&g_cursor[j], 1)] = j;  // self loop
    }
}

// -------------------- tensor-core GEMM + fused attention logits ------------
// h[N,128] = A[N,K](fp16) @ W[K,128](fp16), fp32 accum -> g_hh fp16 + logits.
// 128x128 block, 8 warps (warp tile 32x64), BK=32, mma m16n8k16,
// register-prefetch software pipeline on the global loads.
__device__ __forceinline__ void mma16816(float* c, const unsigned* a,
                                         unsigned b0, unsigned b1) {
    asm volatile(
        "mma.sync.aligned.m16n8k16.row.col.f32.f16.f16.f32 "
        "{%0,%1,%2,%3}, {%4,%5,%6,%7}, {%8,%9}, {%0,%1,%2,%3};"
        : "+f"(c[0]), "+f"(c[1]), "+f"(c[2]), "+f"(c[3])
        : "r"(a[0]), "r"(a[1]), "r"(a[2]), "r"(a[3]), "r"(b0), "r"(b1));
}

__global__ __launch_bounds__(256) void k_gemm(const __half* __restrict__ Ah,
                                              const float* __restrict__ a_s,
                                              const float* __restrict__ a_d,
                                              int w_off, int K) {
    const __half* __restrict__ Wh = g_wh + w_off;
    __shared__ __align__(16) __half sA[128 * 40];   // stride 40 (pad 8)
    __shared__ __align__(16) __half sB[32 * 136];   // stride 136 (pad 8)
    __shared__ float s_red[2][2][128];
    const int tid    = threadIdx.x;
    const int lane   = tid & 31;
    const int wid    = tid >> 5;
    const int warp_m = wid & 3;
    const int warp_n = wid >> 2;
    const int block_row = blockIdx.x * 128;

    // per-thread load coordinates (2 chunks each for A and B)
    int arow[2], ako[2], bkr[2], bno[2];
    #pragma unroll
    for (int l = 0; l < 2; l++) {
        int ch = tid + l * 256;
        arow[l] = ch >> 2;  ako[l] = (ch & 3) * 8;
        bkr[l]  = ch >> 4;  bno[l] = (ch & 15) * 8;
    }

    float c[2][8][4];
    #pragma unroll
    for (int mt = 0; mt < 2; mt++)
        #pragma unroll
        for (int nt = 0; nt < 8; nt++)
            #pragma unroll
            for (int q = 0; q < 4; q++) c[mt][nt][q] = 0.f;

    // prefetch tile 0
    uint4 pa[2], pb[2];
    #pragma unroll
    for (int l = 0; l < 2; l++) {
        int grow = block_row + arow[l];
        pa[l] = make_uint4(0u, 0u, 0u, 0u);
        if (grow < N_NODES)
            pa[l] = *(const uint4*)&Ah[(size_t)grow * K + ako[l]];
        pb[l] = *(const uint4*)&Wh[(size_t)bkr[l] * HID + bno[l]];
    }

    for (int k0 = 0; k0 < K; k0 += 32) {
        #pragma unroll
        for (int l = 0; l < 2; l++) {
            *(uint4*)&sA[arow[l] * 40 + ako[l]]  = pa[l];
            *(uint4*)&sB[bkr[l] * 136 + bno[l]] = pb[l];
        }
        __syncthreads();
        if (k0 + 32 < K) {   // prefetch next tile into regs (overlaps MMAs)
            #pragma unroll
            for (int l = 0; l < 2; l++) {
                int grow = block_row + arow[l];
                pa[l] = make_uint4(0u, 0u, 0u, 0u);
                if (grow < N_NODES)
                    pa[l] = *(const uint4*)&Ah[(size_t)grow * K + k0 + 32 + ako[l]];
                pb[l] = *(const uint4*)&Wh[(size_t)(k0 + 32 + bkr[l]) * HID + bno[l]];
            }
        }
        #pragma unroll
        for (int ks = 0; ks < 2; ks++) {
            unsigned af[2][4];
            #pragma unroll
            for (int mt = 0; mt < 2; mt++) {
                unsigned sa = (unsigned)__cvta_generic_to_shared(
                    &sA[(warp_m * 32 + mt * 16 + (lane & 15)) * 40 +
                        ks * 16 + (lane >> 4) * 8]);
                asm volatile(
                    "ldmatrix.sync.aligned.m8n8.x4.shared.b16 {%0,%1,%2,%3}, [%4];"
                    : "=r"(af[mt][0]), "=r"(af[mt][1]),
                      "=r"(af[mt][2]), "=r"(af[mt][3]) : "r"(sa));
            }
            #pragma unroll
            for (int np = 0; np < 4; np++) {
                unsigned b0, b1, b2, b3;
                unsigned sb = (unsigned)__cvta_generic_to_shared(
                    &sB[(ks * 16 + ((lane >> 3) & 1) * 8 + (lane & 7)) * 136 +
                        warp_n * 64 + np * 16 + (lane >> 4) * 8]);
                asm volatile(
                    "ldmatrix.sync.aligned.m8n8.x4.trans.shared.b16 "
                    "{%0,%1,%2,%3}, [%4];"
                    : "=r"(b0), "=r"(b1), "=r"(b2), "=r"(b3) : "r"(sb));
                #pragma unroll
                for (int mt = 0; mt < 2; mt++) {
                    mma16816(c[mt][2 * np],     af[mt], b0, b1);
                    mma16816(c[mt][2 * np + 1], af[mt], b2, b3);
                }
            }
        }
        __syncthreads();
    }

    // ---- epilogue: store h fp16 + fused attention-logit reduction ----
    float2 as2[8], ad2[8];
    #pragma unroll
    for (int nt = 0; nt < 8; nt++) {
        int n0 = warp_n * 64 + nt * 8 + (lane & 3) * 2;
        as2[nt] = *(const float2*)&a_s[n0];
        ad2[nt] = *(const float2*)&a_d[n0];
    }
    float ps[2][2] = {{0.f, 0.f}, {0.f, 0.f}};
    float pd[2][2] = {{0.f, 0.f}, {0.f, 0.f}};
    #pragma unroll
    for (int mt = 0; mt < 2; mt++) {
        int r0 = block_row + warp_m * 32 + mt * 16 + (lane >> 2);
        #pragma unroll
        for (int nt = 0; nt < 8; nt++) {
            float* cc = c[mt][nt];
            int hcol = warp_n * 32 + nt * 4 + (lane & 3);
            if (r0 < N_NODES)
                g_hh[(size_t)r0 * 64 + hcol] = __floats2half2_rn(cc[0], cc[1]);
            if (r0 + 8 < N_NODES)
                g_hh[(size_t)(r0 + 8) * 64 + hcol] = __floats2half2_rn(cc[2], cc[3]);
            ps[mt][0] += cc[0] * as2[nt].x + cc[1] * as2[nt].y;
            ps[mt][1] += cc[2] * as2[nt].x + cc[3] * as2[nt].y;
            pd[mt][0] += cc[0] * ad2[nt].x + cc[1] * ad2[nt].y;
            pd[mt][1] += cc[2] * ad2[nt].x + cc[3] * ad2[nt].y;
        }
    }
    #pragma unroll
    for (int o = 1; o <= 2; o <<= 1) {
        #pragma unroll
        for (int mt = 0; mt < 2; mt++)
            #pragma unroll
            for (int rh = 0; rh < 2; rh++) {
                ps[mt][rh] += __shfl_xor_sync(0xFFFFFFFFu, ps[mt][rh], o);
                pd[mt][rh] += __shfl_xor_sync(0xFFFFFFFFu, pd[mt][rh], o);
            }
    }
    if ((lane & 3) == 0) {
        #pragma unroll
        for (int mt = 0; mt < 2; mt++)
            #pragma unroll
            for (int rh = 0; rh < 2; rh++) {
                int row = warp_m * 32 + mt * 16 + rh * 8 + (lane >> 2);
                s_red[0][warp_n][row] = ps[mt][rh];
                s_red[1][warp_n][row] = pd[mt][rh];
            }
    }
    __syncthreads();
    if (tid < 128) {
        int grow = block_row + tid;
        if (grow < N_NODES) {
            g_als[grow] = s_red[0][0][tid] + s_red[0][1][tid];
            g_ald[grow] = s_red[1][0][tid] + s_red[1][1][tid];
        }
    }
}

// -------------------- softmax aggregation (one warp per dst node) ----------
__global__ __launch_bounds__(256) void k_agg(const float* __restrict__ bias,
                                             int last) {
    __shared__ float coef[8][128];
    __shared__ int   srcs[8][128];
    const int wid  = threadIdx.x >> 5;
    const int lane = threadIdx.x & 31;
    const int v = blockIdx.x * 8 + wid;
    if (v >= N_NODES) return;
    const int beg = g_rowptr[v];
    const int end = g_rowptr[v + 1];
    const int deg = end - beg;
    const float adv = g_ald[v];

    float m = -1e30f, zpart = 0.f;
    float4 acc = make_float4(0.f, 0.f, 0.f, 0.f);

    if (deg <= 128) {
        // fast path: stage src + leaky logit in smem (single pass over edges)
        for (int i = lane; i < deg; i += 32) {
            int s = g_csrc[beg + i];
            float x = g_als[s] + adv;
            x = (x > 0.f) ? x : NEG_SLOPE * x;
            srcs[wid][i] = s;
            coef[wid][i] = x;
            m = fmaxf(m, x);
        }
        #pragma unroll
        for (int o = 16; o; o >>= 1) m = fmaxf(m, __shfl_xor_sync(0xFFFFFFFFu, m, o));
        for (int i = lane; i < deg; i += 32) {
            float p = __expf(coef[wid][i] - m);
            coef[wid][i] = p;
            zpart += p;
        }
        __syncwarp();
        #pragma unroll 4
        for (int i = 0; i < deg; i++) {
            int s   = srcs[wid][i];
            float p = coef[wid][i];
            uint2 raw = *(const uint2*)&g_hh[(size_t)s * (HID / 2) + lane * 2];
            float2 h0 = __half22float2(*(__half2*)&raw.x);
            float2 h1 = __half22float2(*(__half2*)&raw.y);
            acc.x += p * h0.x; acc.y += p * h0.y;
            acc.z += p * h1.x; acc.w += p * h1.y;
        }
    } else {
        // general path: two-pass, chunked
        for (int e = beg + lane; e < end; e += 32) {
            float x = g_als[g_csrc[e]] + adv;
            x = (x > 0.f) ? x : NEG_SLOPE * x;
            m = fmaxf(m, x);
        }
        #pragma unroll
        for (int o = 16; o; o >>= 1) m = fmaxf(m, __shfl_xor_sync(0xFFFFFFFFu, m, o));
        for (int cb = beg; cb < end; cb += 128) {
            int cnt = min(128, end - cb);
            for (int i = lane; i < cnt; i += 32) {
                int s = g_csrc[cb + i];
                float x = g_als[s] + adv;
                x = (x > 0.f) ? x : NEG_SLOPE * x;
                float p = __expf(x - m);
                coef[wid][i] = p;
                srcs[wid][i] = s;
                zpart += p;
            }
            __syncwarp();
            #pragma unroll 4
            for (int i = 0; i < cnt; i++) {
                int s   = srcs[wid][i];
                float p = coef[wid][i];
                uint2 raw = *(const uint2*)&g_hh[(size_t)s * (HID / 2) + lane * 2];
                float2 h0 = __half22float2(*(__half2*)&raw.x);
                float2 h1 = __half22float2(*(__half2*)&raw.y);
                acc.x += p * h0.x; acc.y += p * h0.y;
                acc.z += p * h1.x; acc.w += p * h1.y;
            }
            __syncwarp();
        }
    }
    #pragma unroll
    for (int o = 16; o; o >>= 1) zpart += __shfl_xor_sync(0xFFFFFFFFu, zpart, o);
    const float inv = 1.f / zpart;   // self-loop guarantees zpart > 0

    float4 bb = *(const float4*)&bias[lane * 4];
    acc.x = acc.x * inv + bb.x;
    acc.y = acc.y * inv + bb.y;
    acc.z = acc.z * inv + bb.z;
    acc.w = acc.w * inv + bb.w;
    if (!last) {   // hidden layers: relu before fp16 store
        acc.x = fmaxf(acc.x, 0.f); acc.y = fmaxf(acc.y, 0.f);
        acc.z = fmaxf(acc.z, 0.f); acc.w = fmaxf(acc.w, 0.f);
    }
    __half2 f0 = __floats2half2_rn(acc.x, acc.y);
    __half2 f1 = __floats2half2_rn(acc.z, acc.w);
    uint2 u;
    u.x = *(unsigned*)&f0;
    u.y = *(unsigned*)&f1;
    *(uint2*)&g_fh[(size_t)v * (HID / 2) + lane * 2] = u;
}

// -------------------- global mean pool (reads fp16 feat) --------------------
__global__ __launch_bounds__(256) void k_pool(const int* __restrict__ batch) {
    __shared__ float s[N_GRAPHS * HID];
    __shared__ float sc[N_GRAPHS];
    const int tid = threadIdx.x;
    for (int i = tid; i < N_GRAPHS * HID; i += 256) s[i] = 0.f;
    if (tid < N_GRAPHS) sc[tid] = 0.f;
    __syncthreads();
    const int wid = tid >> 5, lane = tid & 31;
    for (int v = blockIdx.x * 8 + wid; v < N_NODES; v += gridDim.x * 8) {
        int g = batch[v];
        uint2 raw = *(const uint2*)&g_fh[(size_t)v * (HID / 2) + lane * 2];
        float2 h0 = __half22float2(*(__half2*)&raw.x);
        float2 h1 = __half22float2(*(__half2*)&raw.y);
        float* d = &s[g * HID + lane * 4];
        atomicAdd(d + 0, h0.x); atomicAdd(d + 1, h0.y);
        atomicAdd(d + 2, h1.x); atomicAdd(d + 3, h1.y);
        if (lane == 0) atomicAdd(&sc[g], 1.f);
    }
    __syncthreads();
    for (int i = tid; i < N_GRAPHS * HID; i += 256) atomicAdd(&g_pool[i], s[i]);
    if (tid < N_GRAPHS) atomicAdd(&g_pcnt[tid], sc[tid]);
}

__global__ void k_final(float* __restrict__ out) {
    int i = blockIdx.x * blockDim.x + threadIdx.x;
    if (i < N_GRAPHS * HID)
        out[i] = g_pool[i] / fmaxf(g_pcnt[i / HID], 1.f);
}

// -------------------- launch -----------------------------------------------
extern "C" void kernel_launch(void* const* d_in, const int* in_sizes, int n_in,
                              void* d_out, int out_size) {
    const float* x     = (const float*)d_in[0];
    const int*   ei    = (const int*)d_in[1];
    const int*   batch = (const int*)d_in[2];
    const float* W[3]  = { (const float*)d_in[3], (const float*)d_in[7],  (const float*)d_in[11] };
    const float* AS[3] = { (const float*)d_in[4], (const float*)d_in[8],  (const float*)d_in[12] };
    const float* AD[3] = { (const float*)d_in[5], (const float*)d_in[9],  (const float*)d_in[13] };
    const float* B[3]  = { (const float*)d_in[6], (const float*)d_in[10], (const float*)d_in[14] };
    float* out = (float*)d_out;

    __half *d_xh;
    __half2* d_fh;
    cudaGetSymbolAddress((void**)&d_xh, g_xh);
    cudaGetSymbolAddress((void**)&d_fh, g_fh);

    const int CB = (EV4 + N_NODES + 255) / 256;    // 977
    const int GB = (N_NODES + 127) / 128;          // 391
    const int NB = (N_NODES + 7) / 8;              // 6250

    // prep (all fp16 conversions + zeroing, one kernel)
    k_prep<<<(PREP_TOT + 255) / 256, 256>>>(x, W[0], W[1], W[2]);

    // CSR build (once; shared by all 3 layers)
    k_count<<<CB, 256>>>(ei);
    k_scan<<<1, 1024>>>();
    k_scatter<<<CB, 256>>>(ei);

    // layer 0
    k_gemm<<<GB, 256>>>(d_xh, AS[0], AD[0], 0, IN_DIM);
    k_agg<<<NB, 256>>>(B[0], /*last=*/0);
    // layer 1
    k_gemm<<<GB, 256>>>((const __half*)d_fh, AS[1], AD[1], IN_DIM * HID, HID);
    k_agg<<<NB, 256>>>(B[1], /*last=*/0);
    // layer 2
    k_gemm<<<GB, 256>>>((const __half*)d_fh, AS[2], AD[2],
                        IN_DIM * HID + HID * HID, HID);
    k_agg<<<NB, 256>>>(B[2], /*last=*/1);

    // global mean pool
    k_pool<<<148, 256>>>(batch);
    k_final<<<(N_GRAPHS * HID + 255) / 256, 256>>>(out);
}

// round 12
// speedup vs baseline: 1.7591x; 1.0048x over previous
#include <cuda_runtime.h>
#include <cuda_fp16.h>

// ---------------------------------------------------------------------------
// GAT 3-layer GNN, N=50000 nodes, E=800000 edges (+50000 self loops),
// dims 256->128->128->128, heads=1, leaky_relu(0.2), global mean pool to 16.
// R12: x conversion folded into GEMM-0 loader (fp32->fp16 in-flight);
//      count fused with W-convert; zeroing moved to ticketed pool tail;
//      8-edges/thread CSR build; 10 launches total.
// ---------------------------------------------------------------------------

#define N_NODES 50000
#define N_GRAPHS 16
#define E_EDGES 800000
#define E_TOT   (E_EDGES + N_NODES)
#define IN_DIM  256
#define HID     128
#define NEG_SLOPE 0.2f

// -------------------- device scratch (no allocations allowed) --------------
// Invariant: g_deg, g_pool, g_pcnt, g_tick are ZERO on entry to kernel_launch.
// (zero-initialized at module load; re-zeroed by the k_pool tail each call)
__device__ __half  g_wh[IN_DIM * HID + 2 * HID * HID];     // W0|W1|W2 fp16
__device__ __half2 g_hh[N_NODES * (HID / 2)];              // h (pre-agg) fp16
__device__ __half2 g_fh[N_NODES * (HID / 2)];              // feat fp16
__device__ float   g_als[N_NODES];
__device__ float   g_ald[N_NODES];
__device__ int     g_rowptr[N_NODES + 1];
__device__ int     g_deg[N_NODES];
__device__ int     g_cursor[N_NODES];
__device__ int     g_csrc[E_TOT];
__device__ float   g_pool[N_GRAPHS * HID];
__device__ float   g_pcnt[N_GRAPHS];
__device__ int     g_tick;

// -------------------- helpers ----------------------------------------------
__device__ __forceinline__ void cvt4(const float* __restrict__ s,
                                     __half* __restrict__ d, int i) {
    float4 v = ((const float4*)s)[i];
    __half2 h0 = __floats2half2_rn(v.x, v.y);
    __half2 h1 = __floats2half2_rn(v.z, v.w);
    uint2 o;
    o.x = *(unsigned*)&h0;
    o.y = *(unsigned*)&h1;
    ((uint2*)d)[i] = o;
}

__device__ __forceinline__ uint4 f8_to_h8(float4 a, float4 b) {
    __half2 h0 = __floats2half2_rn(a.x, a.y);
    __half2 h1 = __floats2half2_rn(a.z, a.w);
    __half2 h2 = __floats2half2_rn(b.x, b.y);
    __half2 h3 = __floats2half2_rn(b.z, b.w);
    uint4 u;
    u.x = *(unsigned*)&h0; u.y = *(unsigned*)&h1;
    u.z = *(unsigned*)&h2; u.w = *(unsigned*)&h3;
    return u;
}

// -------------------- prep: degree count + W fp16 conversion ----------------
#define EV8 (E_EDGES / 8)              // 100,000
#define W04 (IN_DIM * HID / 4)         // 8,192
#define W14 (HID * HID / 4)            // 4,096
#define PREP_TOT (EV8 + N_NODES + W04 + 2 * W14)

__global__ void k_prepcount(const int* __restrict__ ei,
                            const float* __restrict__ w0,
                            const float* __restrict__ w1,
                            const float* __restrict__ w2) {
    int i = blockIdx.x * blockDim.x + threadIdx.x;
    if (i < EV8) {   // 8 edge-dst counts per thread (g_deg pre-zeroed)
        const int4* d4 = (const int4*)(ei + E_EDGES);
        int4 a = d4[2 * i], b = d4[2 * i + 1];
        atomicAdd(&g_deg[a.x], 1); atomicAdd(&g_deg[a.y], 1);
        atomicAdd(&g_deg[a.z], 1); atomicAdd(&g_deg[a.w], 1);
        atomicAdd(&g_deg[b.x], 1); atomicAdd(&g_deg[b.y], 1);
        atomicAdd(&g_deg[b.z], 1); atomicAdd(&g_deg[b.w], 1);
        return;
    }
    i -= EV8;
    if (i < N_NODES) { atomicAdd(&g_deg[i], 1); return; }   // self loop
    i -= N_NODES;
    if (i < W04) { cvt4(w0, g_wh, i); return; }
    i -= W04;
    if (i < W14) { cvt4(w1, g_wh + IN_DIM * HID, i); return; }
    i -= W14;
    if (i < W14) cvt4(w2, g_wh + IN_DIM * HID + HID * HID, i);
}

// -------------------- exclusive scan of degrees -----------------------------
__global__ void k_scan() {
    __shared__ int s[1024];
    const int t = threadIdx.x;
    const int CH = (N_NODES + 1023) / 1024;   // 49
    const int base = t * CH;
    int sum = 0;
    for (int i = 0; i < CH; i++) {
        int v = base + i;
        if (v < N_NODES) sum += g_deg[v];
    }
    s[t] = sum;
    __syncthreads();
    for (int off = 1; off < 1024; off <<= 1) {
        int v = (t >= off) ? s[t - off] : 0;
        __syncthreads();
        s[t] += v;
        __syncthreads();
    }
    int run = (t > 0) ? s[t - 1] : 0;
    for (int i = 0; i < CH; i++) {
        int v = base + i;
        if (v < N_NODES) {
            g_rowptr[v] = run;
            g_cursor[v] = run;
            run += g_deg[v];
        }
    }
    if (t == 1023) g_rowptr[N_NODES] = s[1023];
}

// -------------------- scatter (8 edges/thread) ------------------------------
__global__ void k_scatter(const int* __restrict__ ei) {
    int i = blockIdx.x * blockDim.x + threadIdx.x;
    if (i < EV8) {
        const int4* s4 = (const int4*)ei;
        const int4* d4 = (const int4*)(ei + E_EDGES);
        int4 sa = s4[2 * i], sb = s4[2 * i + 1];
        int4 da = d4[2 * i], db = d4[2 * i + 1];
        g_csrc[atomicAdd(&g_cursor[da.x], 1)] = sa.x;
        g_csrc[atomicAdd(&g_cursor[da.y], 1)] = sa.y;
        g_csrc[atomicAdd(&g_cursor[da.z], 1)] = sa.z;
        g_csrc[atomicAdd(&g_cursor[da.w], 1)] = sa.w;
        g_csrc[atomicAdd(&g_cursor[db.x], 1)] = sb.x;
        g_csrc[atomicAdd(&g_cursor[db.y], 1)] = sb.y;
        g_csrc[atomicAdd(&g_cursor[db.z], 1)] = sb.z;
        g_csrc[atomicAdd(&g_cursor[db.w], 1)] = sb.w;
    } else {
        int j = i - EV8;
        if (j < N_NODES) g_csrc[atomicAdd(&g_cursor[j], 1)] = j;  // self loop
    }
}

// -------------------- tensor-core GEMM + fused attention logits ------------
// h[N,128] = A[N,K] @ W[K,128] (fp16 mma, fp32 accum) -> g_hh fp16 + logits.
// AF32: A is fp32 in gmem, converted to fp16 while staging to smem.
__device__ __forceinline__ void mma16816(float* c, const unsigned* a,
                                         unsigned b0, unsigned b1) {
    asm volatile(
        "mma.sync.aligned.m16n8k16.row.col.f32.f16.f16.f32 "
        "{%0,%1,%2,%3}, {%4,%5,%6,%7}, {%8,%9}, {%0,%1,%2,%3};"
        : "+f"(c[0]), "+f"(c[1]), "+f"(c[2]), "+f"(c[3])
        : "r"(a[0]), "r"(a[1]), "r"(a[2]), "r"(a[3]), "r"(b0), "r"(b1));
}

template <int AF32>
__global__ __launch_bounds__(256) void k_gemm(const __half* __restrict__ Ah,
                                              const float* __restrict__ Af,
                                              const float* __restrict__ a_s,
                                              const float* __restrict__ a_d,
                                              int w_off, int K) {
    const __half* __restrict__ Wh = g_wh + w_off;
    __shared__ __align__(16) __half sA[128 * 40];   // stride 40 (pad 8)
    __shared__ __align__(16) __half sB[32 * 136];   // stride 136 (pad 8)
    __shared__ float s_red[2][2][128];
    const int tid    = threadIdx.x;
    const int lane   = tid & 31;
    const int wid    = tid >> 5;
    const int warp_m = wid & 3;
    const int warp_n = wid >> 2;
    const int block_row = blockIdx.x * 128;

    int arow[2], ako[2], bkr[2], bno[2];
    #pragma unroll
    for (int l = 0; l < 2; l++) {
        int ch = tid + l * 256;
        arow[l] = ch >> 2;  ako[l] = (ch & 3) * 8;
        bkr[l]  = ch >> 4;  bno[l] = (ch & 15) * 8;
    }

    float c[2][8][4];
    #pragma unroll
    for (int mt = 0; mt < 2; mt++)
        #pragma unroll
        for (int nt = 0; nt < 8; nt++)
            #pragma unroll
            for (int q = 0; q < 4; q++) c[mt][nt][q] = 0.f;

    // prefetch tile 0
    uint4 pa[2], pb[2];
    #pragma unroll
    for (int l = 0; l < 2; l++) {
        int grow = block_row + arow[l];
        if (AF32) {
            float4 f0 = make_float4(0.f, 0.f, 0.f, 0.f), f1 = f0;
            if (grow < N_NODES) {
                f0 = *(const float4*)&Af[(size_t)grow * K + ako[l]];
                f1 = *(const float4*)&Af[(size_t)grow * K + ako[l] + 4];
            }
            pa[l] = f8_to_h8(f0, f1);
        } else {
            pa[l] = make_uint4(0u, 0u, 0u, 0u);
            if (grow < N_NODES)
                pa[l] = *(const uint4*)&Ah[(size_t)grow * K + ako[l]];
        }
        pb[l] = *(const uint4*)&Wh[(size_t)bkr[l] * HID + bno[l]];
    }

    for (int k0 = 0; k0 < K; k0 += 32) {
        #pragma unroll
        for (int l = 0; l < 2; l++) {
            *(uint4*)&sA[arow[l] * 40 + ako[l]]  = pa[l];
            *(uint4*)&sB[bkr[l] * 136 + bno[l]] = pb[l];
        }
        __syncthreads();
        if (k0 + 32 < K) {   // prefetch next tile into regs (overlaps MMAs)
            #pragma unroll
            for (int l = 0; l < 2; l++) {
                int grow = block_row + arow[l];
                if (AF32) {
                    float4 f0 = make_float4(0.f, 0.f, 0.f, 0.f), f1 = f0;
                    if (grow < N_NODES) {
                        f0 = *(const float4*)&Af[(size_t)grow * K + k0 + 32 + ako[l]];
                        f1 = *(const float4*)&Af[(size_t)grow * K + k0 + 36 + ako[l]];
                    }
                    pa[l] = f8_to_h8(f0, f1);
                } else {
                    pa[l] = make_uint4(0u, 0u, 0u, 0u);
                    if (grow < N_NODES)
                        pa[l] = *(const uint4*)&Ah[(size_t)grow * K + k0 + 32 + ako[l]];
                }
                pb[l] = *(const uint4*)&Wh[(size_t)(k0 + 32 + bkr[l]) * HID + bno[l]];
            }
        }
        #pragma unroll
        for (int ks = 0; ks < 2; ks++) {
            unsigned af[2][4];
            #pragma unroll
            for (int mt = 0; mt < 2; mt++) {
                unsigned sa = (unsigned)__cvta_generic_to_shared(
                    &sA[(warp_m * 32 + mt * 16 + (lane & 15)) * 40 +
                        ks * 16 + (lane >> 4) * 8]);
                asm volatile(
                    "ldmatrix.sync.aligned.m8n8.x4.shared.b16 {%0,%1,%2,%3}, [%4];"
                    : "=r"(af[mt][0]), "=r"(af[mt][1]),
                      "=r"(af[mt][2]), "=r"(af[mt][3]) : "r"(sa));
            }
            #pragma unroll
            for (int np = 0; np < 4; np++) {
                unsigned b0, b1, b2, b3;
                unsigned sb = (unsigned)__cvta_generic_to_shared(
                    &sB[(ks * 16 + ((lane >> 3) & 1) * 8 + (lane & 7)) * 136 +
                        warp_n * 64 + np * 16 + (lane >> 4) * 8]);
                asm volatile(
                    "ldmatrix.sync.aligned.m8n8.x4.trans.shared.b16 "
                    "{%0,%1,%2,%3}, [%4];"
                    : "=r"(b0), "=r"(b1), "=r"(b2), "=r"(b3) : "r"(sb));
                #pragma unroll
                for (int mt = 0; mt < 2; mt++) {
                    mma16816(c[mt][2 * np],     af[mt], b0, b1);
                    mma16816(c[mt][2 * np + 1], af[mt], b2, b3);
                }
            }
        }
        __syncthreads();
    }

    // ---- epilogue: store h fp16 + fused attention-logit reduction ----
    float2 as2[8], ad2[8];
    #pragma unroll
    for (int nt = 0; nt < 8; nt++) {
        int n0 = warp_n * 64 + nt * 8 + (lane & 3) * 2;
        as2[nt] = *(const float2*)&a_s[n0];
        ad2[nt] = *(const float2*)&a_d[n0];
    }
    float ps[2][2] = {{0.f, 0.f}, {0.f, 0.f}};
    float pd[2][2] = {{0.f, 0.f}, {0.f, 0.f}};
    #pragma unroll
    for (int mt = 0; mt < 2; mt++) {
        int r0 = block_row + warp_m * 32 + mt * 16 + (lane >> 2);
        #pragma unroll
        for (int nt = 0; nt < 8; nt++) {
            float* cc = c[mt][nt];
            int hcol = warp_n * 32 + nt * 4 + (lane & 3);
            if (r0 < N_NODES)
                g_hh[(size_t)r0 * 64 + hcol] = __floats2half2_rn(cc[0], cc[1]);
            if (r0 + 8 < N_NODES)
                g_hh[(size_t)(r0 + 8) * 64 + hcol] = __floats2half2_rn(cc[2], cc[3]);
            ps[mt][0] += cc[0] * as2[nt].x + cc[1] * as2[nt].y;
            ps[mt][1] += cc[2] * as2[nt].x + cc[3] * as2[nt].y;
            pd[mt][0] += cc[0] * ad2[nt].x + cc[1] * ad2[nt].y;
            pd[mt][1] += cc[2] * ad2[nt].x + cc[3] * ad2[nt].y;
        }
    }
    #pragma unroll
    for (int o = 1; o <= 2; o <<= 1) {
        #pragma unroll
        for (int mt = 0; mt < 2; mt++)
            #pragma unroll
            for (int rh = 0; rh < 2; rh++) {
                ps[mt][rh] += __shfl_xor_sync(0xFFFFFFFFu, ps[mt][rh], o);
                pd[mt][rh] += __shfl_xor_sync(0xFFFFFFFFu, pd[mt][rh], o);
            }
    }
    if ((lane & 3) == 0) {
        #pragma unroll
        for (int mt = 0; mt < 2; mt++)
            #pragma unroll
            for (int rh = 0; rh < 2; rh++) {
                int row = warp_m * 32 + mt * 16 + rh * 8 + (lane >> 2);
                s_red[0][warp_n][row] = ps[mt][rh];
                s_red[1][warp_n][row] = pd[mt][rh];
            }
    }
    __syncthreads();
    if (tid < 128) {
        int grow = block_row + tid;
        if (grow < N_NODES) {
            g_als[grow] = s_red[0][0][tid] + s_red[0][1][tid];
            g_ald[grow] = s_red[1][0][tid] + s_red[1][1][tid];
        }
    }
}

// -------------------- softmax aggregation (one warp per dst node) ----------
__global__ __launch_bounds__(256) void k_agg(const float* __restrict__ bias,
                                             int last) {
    __shared__ float coef[8][128];
    __shared__ int   srcs[8][128];
    const int wid  = threadIdx.x >> 5;
    const int lane = threadIdx.x & 31;
    const int v = blockIdx.x * 8 + wid;
    if (v >= N_NODES) return;
    const int beg = g_rowptr[v];
    const int end = g_rowptr[v + 1];
    const int deg = end - beg;
    const float adv = g_ald[v];

    float m = -1e30f, zpart = 0.f;
    float4 acc = make_float4(0.f, 0.f, 0.f, 0.f);

    if (deg <= 128) {
        for (int i = lane; i < deg; i += 32) {
            int s = g_csrc[beg + i];
            float x = g_als[s] + adv;
            x = (x > 0.f) ? x : NEG_SLOPE * x;
            srcs[wid][i] = s;
            coef[wid][i] = x;
            m = fmaxf(m, x);
        }
        #pragma unroll
        for (int o = 16; o; o >>= 1) m = fmaxf(m, __shfl_xor_sync(0xFFFFFFFFu, m, o));
        for (int i = lane; i < deg; i += 32) {
            float p = __expf(coef[wid][i] - m);
            coef[wid][i] = p;
            zpart += p;
        }
        __syncwarp();
        #pragma unroll 4
        for (int i = 0; i < deg; i++) {
            int s   = srcs[wid][i];
            float p = coef[wid][i];
            uint2 raw = *(const uint2*)&g_hh[(size_t)s * (HID / 2) + lane * 2];
            float2 h0 = __half22float2(*(__half2*)&raw.x);
            float2 h1 = __half22float2(*(__half2*)&raw.y);
            acc.x += p * h0.x; acc.y += p * h0.y;
            acc.z += p * h1.x; acc.w += p * h1.y;
        }
    } else {
        for (int e = beg + lane; e < end; e += 32) {
            float x = g_als[g_csrc[e]] + adv;
            x = (x > 0.f) ? x : NEG_SLOPE * x;
            m = fmaxf(m, x);
        }
        #pragma unroll
        for (int o = 16; o; o >>= 1) m = fmaxf(m, __shfl_xor_sync(0xFFFFFFFFu, m, o));
        for (int cb = beg; cb < end; cb += 128) {
            int cnt = min(128, end - cb);
            for (int i = lane; i < cnt; i += 32) {
                int s = g_csrc[cb + i];
                float x = g_als[s] + adv;
                x = (x > 0.f) ? x : NEG_SLOPE * x;
                float p = __expf(x - m);
                coef[wid][i] = p;
                srcs[wid][i] = s;
                zpart += p;
            }
            __syncwarp();
            #pragma unroll 4
            for (int i = 0; i < cnt; i++) {
                int s   = srcs[wid][i];
                float p = coef[wid][i];
                uint2 raw = *(const uint2*)&g_hh[(size_t)s * (HID / 2) + lane * 2];
                float2 h0 = __half22float2(*(__half2*)&raw.x);
                float2 h1 = __half22float2(*(__half2*)&raw.y);
                acc.x += p * h0.x; acc.y += p * h0.y;
                acc.z += p * h1.x; acc.w += p * h1.y;
            }
            __syncwarp();
        }
    }
    #pragma unroll
    for (int o = 16; o; o >>= 1) zpart += __shfl_xor_sync(0xFFFFFFFFu, zpart, o);
    const float inv = 1.f / zpart;   // self-loop guarantees zpart > 0

    float4 bb = *(const float4*)&bias[lane * 4];
    acc.x = acc.x * inv + bb.x;
    acc.y = acc.y * inv + bb.y;
    acc.z = acc.z * inv + bb.z;
    acc.w = acc.w * inv + bb.w;
    if (!last) {
        acc.x = fmaxf(acc.x, 0.f); acc.y = fmaxf(acc.y, 0.f);
        acc.z = fmaxf(acc.z, 0.f); acc.w = fmaxf(acc.w, 0.f);
    }
    __half2 f0 = __floats2half2_rn(acc.x, acc.y);
    __half2 f1 = __floats2half2_rn(acc.z, acc.w);
    uint2 u;
    u.x = *(unsigned*)&f0;
    u.y = *(unsigned*)&f1;
    *(uint2*)&g_fh[(size_t)v * (HID / 2) + lane * 2] = u;
}

// ---------- global mean pool + final divide + scratch re-zero (tail) -------
__global__ __launch_bounds__(256) void k_pool(const int* __restrict__ batch,
                                              float* __restrict__ out) {
    __shared__ float s[N_GRAPHS * HID];
    __shared__ float sc[N_GRAPHS];
    __shared__ int isLast;
    const int tid = threadIdx.x;
    for (int i = tid; i < N_GRAPHS * HID; i += 256) s[i] = 0.f;
    if (tid < N_GRAPHS) sc[tid] = 0.f;
    __syncthreads();
    const int wid = tid >> 5, lane = tid & 31;
    for (int v = blockIdx.x * 8 + wid; v < N_NODES; v += gridDim.x * 8) {
        int g = batch[v];
        uint2 raw = *(const uint2*)&g_fh[(size_t)v * (HID / 2) + lane * 2];
        float2 h0 = __half22float2(*(__half2*)&raw.x);
        float2 h1 = __half22float2(*(__half2*)&raw.y);
        float* d = &s[g * HID + lane * 4];
        atomicAdd(d + 0, h0.x); atomicAdd(d + 1, h0.y);
        atomicAdd(d + 2, h1.x); atomicAdd(d + 3, h1.y);
        if (lane == 0) atomicAdd(&sc[g], 1.f);
    }
    __syncthreads();
    for (int i = tid; i < N_GRAPHS * HID; i += 256) atomicAdd(&g_pool[i], s[i]);
    if (tid < N_GRAPHS) atomicAdd(&g_pcnt[tid], sc[tid]);

    // ticketed tail: last block finalizes output and re-zeroes scratch
    __threadfence();
    __syncthreads();
    if (tid == 0) isLast = (atomicAdd(&g_tick, 1) == (int)gridDim.x - 1);
    __syncthreads();
    if (isLast) {
        for (int i = tid; i < N_GRAPHS * HID; i += 256)
            out[i] = g_pool[i] / fmaxf(g_pcnt[i / HID], 1.f);
        __syncthreads();
        for (int i = tid; i < N_GRAPHS * HID; i += 256) g_pool[i] = 0.f;
        if (tid < N_GRAPHS) g_pcnt[tid] = 0.f;
        for (int i = tid; i < N_NODES; i += 256) g_deg[i] = 0;
        if (tid == 0) g_tick = 0;
    }
}

// -------------------- launch -----------------------------------------------
extern "C" void kernel_launch(void* const* d_in, const int* in_sizes, int n_in,
                              void* d_out, int out_size) {
    const float* x     = (const float*)d_in[0];
    const int*   ei    = (const int*)d_in[1];
    const int*   batch = (const int*)d_in[2];
    const float* W[3]  = { (const float*)d_in[3], (const float*)d_in[7],  (const float*)d_in[11] };
    const float* AS[3] = { (const float*)d_in[4], (const float*)d_in[8],  (const float*)d_in[12] };
    const float* AD[3] = { (const float*)d_in[5], (const float*)d_in[9],  (const float*)d_in[13] };
    const float* B[3]  = { (const float*)d_in[6], (const float*)d_in[10], (const float*)d_in[14] };
    float* out = (float*)d_out;

    __half2* d_fh;
    cudaGetSymbolAddress((void**)&d_fh, g_fh);

    const int PB = (PREP_TOT + 255) / 256;             // 650
    const int SB = (EV8 + N_NODES + 255) / 256;        // 586
    const int GB = (N_NODES + 127) / 128;              // 391
    const int NB = (N_NODES + 7) / 8;                  // 6250

    // CSR build + W conversion (deg pre-zeroed by previous call's tail)
    k_prepcount<<<PB, 256>>>(ei, W[0], W[1], W[2]);
    k_scan<<<1, 1024>>>();
    k_scatter<<<SB, 256>>>(ei);

    // layer 0 (A = fp32 x, converted in the loader)
    k_gemm<1><<<GB, 256>>>(nullptr, x, AS[0], AD[0], 0, IN_DIM);
    k_agg<<<NB, 256>>>(B[0], /*last=*/0);
    // layer 1
    k_gemm<0><<<GB, 256>>>((const __half*)d_fh, nullptr, AS[1], AD[1],
                           IN_DIM * HID, HID);
    k_agg<<<NB, 256>>>(B[1], /*last=*/0);
    // layer 2
    k_gemm<0><<<GB, 256>>>((const __half*)d_fh, nullptr, AS[2], AD[2],
                           IN_DIM * HID + HID * HID, HID);
    k_agg<<<NB, 256>>>(B[2], /*last=*/1);

    // pool + final + scratch re-zero (ticketed tail block)
    k_pool<<<148, 256>>>(batch, out);
}